// round 2
// baseline (speedup 1.0000x reference)
#include <cuda_runtime.h>

// LocalAtomAttention fused kernel (round 2: fp32 SIMT baseline, mask as int32)
//
// Shapes: x [B,L,A,C] = [16,4096,4,128] f32; mask [B,L,A] bool delivered as
// int32 (harness dtype set is {f32,i32,bf16}); W* [128,128] f32 row-major
// [c_out][c_in]; b* [128].
// Per residue: q/k/v = x@W^T+b, 4 heads x 32 dim, 4x4 masked softmax attention,
// out-proj, residue mask.
//
// CTA = 16 residues = 64 atom-tokens. smem: X/Q/K/V tiles [64][132] + W stage
// [128][132] (~198 KB). GEMM mapping: warp w owns tokens {w+8j}, lane l owns
// channels {l+32i}; weight float4 LDS conflict-free at stride 132, X reads are
// warp-broadcast. FMA-pipe bound by design.

namespace {
constexpr int C_   = 128;   // channels
constexpr int S_   = 132;   // smem row stride in floats (bank-conflict avoidance)
constexpr int TOK_ = 64;    // tokens per block (16 residues * 4 atoms)
constexpr int NT_  = 256;   // threads per block
constexpr int SMEM_BYTES = (4 * TOK_ * S_ + C_ * S_) * 4 + 128;  // X,Q,K,V,W + mask
}

template<bool FINAL>
__device__ __forceinline__ void project_tile(
    const float* __restrict__ Wg, const float* __restrict__ bg,
    const float* __restrict__ Xs, float* __restrict__ Ws,
    float* __restrict__ dst,
    const unsigned char* __restrict__ msk,
    float* __restrict__ gout, long long tok0,
    int t, int lane, int w)
{
    // Stage weights: W[c_out][c_in] row-major -> Ws[c][k], coalesced float4.
    for (int i = t; i < C_ * (C_ / 4); i += NT_) {
        int r = i >> 5;
        int c4 = (i & 31) << 2;
        *(float4*)&Ws[r * S_ + c4] = *(const float4*)&Wg[r * C_ + c4];
    }
    __syncthreads();  // Ws ready; also orders any prior smem writes before reads.

    float acc[8][4];
#pragma unroll
    for (int j = 0; j < 8; ++j)
#pragma unroll
        for (int i = 0; i < 4; ++i) acc[j][i] = 0.f;

#pragma unroll 2
    for (int kc = 0; kc < C_ / 4; ++kc) {
        const int k = kc * 4;
        float4 wv[4];
#pragma unroll
        for (int i = 0; i < 4; ++i)
            wv[i] = *(const float4*)&Ws[(lane + 32 * i) * S_ + k];  // conflict-free
#pragma unroll
        for (int j = 0; j < 8; ++j) {
            float4 xv = *(const float4*)&Xs[(w + 8 * j) * S_ + k];  // warp-broadcast
#pragma unroll
            for (int i = 0; i < 4; ++i) {
                acc[j][i] = fmaf(xv.x, wv[i].x, acc[j][i]);
                acc[j][i] = fmaf(xv.y, wv[i].y, acc[j][i]);
                acc[j][i] = fmaf(xv.z, wv[i].z, acc[j][i]);
                acc[j][i] = fmaf(xv.w, wv[i].w, acc[j][i]);
            }
        }
    }

    float bias[4];
#pragma unroll
    for (int i = 0; i < 4; ++i) bias[i] = __ldg(&bg[lane + 32 * i]);

    if (FINAL) {
#pragma unroll
        for (int j = 0; j < 8; ++j) {
            const int tok = w + 8 * j;
            const int r4 = (tok >> 2) * 4;
            const float rm =
                (msk[r4] | msk[r4 + 1] | msk[r4 + 2] | msk[r4 + 3]) ? 1.f : 0.f;
#pragma unroll
            for (int i = 0; i < 4; ++i)
                gout[(tok0 + tok) * C_ + lane + 32 * i] = (acc[j][i] + bias[i]) * rm;
        }
    } else {
#pragma unroll
        for (int j = 0; j < 8; ++j) {
            const int tok = w + 8 * j;
#pragma unroll
            for (int i = 0; i < 4; ++i)
                dst[tok * S_ + lane + 32 * i] = acc[j][i] + bias[i];  // conflict-free
        }
        __syncthreads();  // tile ready for next consumer
    }
}

__global__ __launch_bounds__(NT_, 1)
void laa_fused_kernel(
    const float* __restrict__ x, const int* __restrict__ mask,
    const float* __restrict__ Wq, const float* __restrict__ bq,
    const float* __restrict__ Wk, const float* __restrict__ bk,
    const float* __restrict__ Wv, const float* __restrict__ bv,
    const float* __restrict__ Wo, const float* __restrict__ bo,
    float* __restrict__ out)
{
    extern __shared__ float sm[];
    float* Xs = sm;
    float* Qs = Xs + TOK_ * S_;
    float* Ks = Qs + TOK_ * S_;
    float* Vs = Ks + TOK_ * S_;
    float* Ws = Vs + TOK_ * S_;
    unsigned char* msk = (unsigned char*)(Ws + C_ * S_);

    const int t = threadIdx.x;
    const int lane = t & 31;
    const int w = t >> 5;
    const long long tok0 = (long long)blockIdx.x * TOK_;

    // Load X tile [64][128] coalesced.
    for (int i = t; i < TOK_ * (C_ / 4); i += NT_) {
        int tok = i >> 5;
        int c4 = (i & 31) << 2;
        *(float4*)&Xs[tok * S_ + c4] = *(const float4*)&x[(tok0 + tok) * C_ + c4];
    }
    // mask arrives as int32 (one int per atom); booleanize into smem bytes.
    if (t < TOK_) msk[t] = (unsigned char)(mask[tok0 + t] != 0);
    // (project_tile's staging __syncthreads orders these before first use)

    project_tile<false>(Wq, bq, Xs, Ws, Qs, msk, nullptr, tok0, t, lane, w);
    project_tile<false>(Wk, bk, Xs, Ws, Ks, msk, nullptr, tok0, t, lane, w);
    project_tile<false>(Wv, bv, Xs, Ws, Vs, msk, nullptr, tok0, t, lane, w);

    // ---- Attention: thread -> (residue, head, q_atom); 16*4*4 = 256 threads ----
    {
        const int res = t & 15;
        const int sub = t >> 4;
        const int h = sub & 3;
        const int qa = sub >> 2;
        const int tq = res * 4 + qa;
        const int hb = h * 32;

        float s[4];
#pragma unroll
        for (int ka = 0; ka < 4; ++ka) {
            float a = 0.f;
            const float* qp = &Qs[tq * S_ + hb];
            const float* kp = &Ks[(res * 4 + ka) * S_ + hb];
#pragma unroll
            for (int d4 = 0; d4 < 8; ++d4) {
                float4 qv = *(const float4*)&qp[d4 * 4];
                float4 kv = *(const float4*)&kp[d4 * 4];
                a = fmaf(qv.x, kv.x, a);
                a = fmaf(qv.y, kv.y, a);
                a = fmaf(qv.z, kv.z, a);
                a = fmaf(qv.w, kv.w, a);
            }
            // scale = 1/sqrt(32); masked-out keys get -inf-equivalent bias
            s[ka] = msk[res * 4 + ka] ? a * 0.17677669529663687f : -1e30f;
        }
        const float m = fmaxf(fmaxf(s[0], s[1]), fmaxf(s[2], s[3]));
        float p[4], psum = 0.f;
#pragma unroll
        for (int ka = 0; ka < 4; ++ka) {
            p[ka] = __expf(s[ka] - m);
            psum += p[ka];
        }
        const float inv = 1.f / psum;

        float4 o[8];
#pragma unroll
        for (int d4 = 0; d4 < 8; ++d4) o[d4] = make_float4(0.f, 0.f, 0.f, 0.f);
#pragma unroll
        for (int ka = 0; ka < 4; ++ka) {
            const float pw = p[ka] * inv;
            const float* vp = &Vs[(res * 4 + ka) * S_ + hb];
#pragma unroll
            for (int d4 = 0; d4 < 8; ++d4) {
                float4 vv = *(const float4*)&vp[d4 * 4];
                o[d4].x = fmaf(pw, vv.x, o[d4].x);
                o[d4].y = fmaf(pw, vv.y, o[d4].y);
                o[d4].z = fmaf(pw, vv.z, o[d4].z);
                o[d4].w = fmaf(pw, vv.w, o[d4].w);
            }
        }
        // Overwrite X tile (no longer needed) with attention output.
#pragma unroll
        for (int d4 = 0; d4 < 8; ++d4)
            *(float4*)&Xs[tq * S_ + hb + d4 * 4] = o[d4];
        // project_tile<true>'s staging __syncthreads orders these writes
        // before the final GEMM reads Xs.
    }

    project_tile<true>(Wo, bo, Xs, Ws, nullptr, msk, out, tok0, t, lane, w);
}

extern "C" void kernel_launch(void* const* d_in, const int* in_sizes, int n_in,
                              void* d_out, int out_size)
{
    const float* x    = (const float*)d_in[0];
    const int*   mask = (const int*)d_in[1];
    const float* Wq = (const float*)d_in[2];
    const float* bq = (const float*)d_in[3];
    const float* Wk = (const float*)d_in[4];
    const float* bk = (const float*)d_in[5];
    const float* Wv = (const float*)d_in[6];
    const float* bv = (const float*)d_in[7];
    const float* Wo = (const float*)d_in[8];
    const float* bo = (const float*)d_in[9];
    float* out = (float*)d_out;

    const int ntok = in_sizes[0] / C_;   // 262144
    const int nblk = ntok / TOK_;        // 4096

    cudaFuncSetAttribute(laa_fused_kernel,
                         cudaFuncAttributeMaxDynamicSharedMemorySize, SMEM_BYTES);

    laa_fused_kernel<<<nblk, NT_, SMEM_BYTES>>>(
        x, mask, Wq, bq, Wk, bk, Wv, bv, Wo, bo, out);
}

// round 5
// speedup vs baseline: 3.2776x; 3.2776x over previous
#include <cuda_runtime.h>
#include <cuda_bf16.h>
#include <cuda_fp16.h>
#include <cstdint>

// LocalAtomAttention (round 5): warp-level mma.sync bf16x3, unfused 4-GEMM.
// Q = x·(s·Wq)^T + s·bq   (fp16 in smem)
// K = x·Wk^T + bk         (fp16 in smem)
// V = x·Wv^T + bv         (bf16 hi/lo, overwrites dead X tiles)
// attention per (residue, head, q_atom) thread -> Y (bf16 hi/lo into Q/K tiles)
// out = Y·Wo^T + bo, × residue mask.

namespace laa {
constexpr int C = 128, TOKS = 128, NT = 512;
constexpr uint32_t RS = 272;  // smem row stride bytes (conflict-free ldmatrix)
constexpr uint32_t XH = 0, XL = 34816, WHO = 69632, WLO = 104448,
                   QHO = 139264, KHO = 174080, MSK = 208896, RM = 209408,
                   TOTAL = 209920;
constexpr float SCALE = 0.17677669529663687f;  // 1/sqrt(32)
}

// Prepped weights: [4] = {Wq*s, Wk, Wv, Wo}, each hi(34816B)+lo(34816B), 272B rows.
__device__ __align__(16) unsigned char g_wimg[4][69632];
__device__ float g_bias[4][128];   // {bq*s, bk, bv, bo}

// ---------------- helpers ----------------
__device__ __forceinline__ uint32_t smem_u32(const void* p) {
    uint32_t a;
    asm("{ .reg .u64 t; cvta.to.shared.u64 t, %1; cvt.u32.u64 %0, t; }" : "=r"(a) : "l"(p));
    return a;
}
__device__ __forceinline__ uint32_t pkbf(float a, float b) {
    __nv_bfloat162 t = __floats2bfloat162_rn(a, b);
    return *(uint32_t*)&t;
}
__device__ __forceinline__ void ldsm4(uint32_t& a0, uint32_t& a1, uint32_t& a2,
                                      uint32_t& a3, uint32_t addr) {
    asm volatile("ldmatrix.sync.aligned.m8n8.x4.shared.b16 {%0,%1,%2,%3}, [%4];"
                 : "=r"(a0), "=r"(a1), "=r"(a2), "=r"(a3) : "r"(addr));
}
__device__ __forceinline__ void mma16816(float d[4], uint32_t a0, uint32_t a1,
                                         uint32_t a2, uint32_t a3,
                                         uint32_t b0, uint32_t b1) {
    asm volatile(
        "mma.sync.aligned.m16n8k16.row.col.f32.bf16.bf16.f32 "
        "{%0,%1,%2,%3}, {%4,%5,%6,%7}, {%8,%9}, {%0,%1,%2,%3};"
        : "+f"(d[0]), "+f"(d[1]), "+f"(d[2]), "+f"(d[3])
        : "r"(a0), "r"(a1), "r"(a2), "r"(a3), "r"(b0), "r"(b1));
}

// ---------------- prep kernel ----------------
__global__ void prep_split(const float* __restrict__ Wq, const float* __restrict__ bq,
                           const float* __restrict__ Wk, const float* __restrict__ bk,
                           const float* __restrict__ Wv, const float* __restrict__ bv,
                           const float* __restrict__ Wo, const float* __restrict__ bo) {
    int m = blockIdx.x;
    const float* src  = (m == 0) ? Wq : (m == 1) ? Wk : (m == 2) ? Wv : Wo;
    const float* bsrc = (m == 0) ? bq : (m == 1) ? bk : (m == 2) ? bv : bo;
    float sc = (m == 0) ? laa::SCALE : 1.f;
    unsigned char* img = g_wimg[m];
    for (int i = threadIdx.x; i < 16384; i += blockDim.x) {
        int row = i >> 7, col = i & 127;
        float f = src[i] * sc;
        __nv_bfloat16 h = __float2bfloat16(f);
        __nv_bfloat16 l = __float2bfloat16(f - __bfloat162float(h));
        *(__nv_bfloat16*)(img + row * laa::RS + col * 2) = h;
        *(__nv_bfloat16*)(img + 34816 + row * laa::RS + col * 2) = l;
    }
    if (threadIdx.x < 128) g_bias[m][threadIdx.x] = bsrc[threadIdx.x] * sc;
}

// ---------------- main kernel ----------------
using namespace laa;

// Warp GEMM: D[16 rows x 8 ntiles] += (Ah+Al)·(Bh+Bl)^T (3-term bf16 split).
__device__ __forceinline__ void warp_gemm3(uint32_t ah_t, uint32_t al_t,
                                           uint32_t wh, uint32_t wl,
                                           int r0, int ntb, float d[8][4], int lane) {
    const uint32_t aoff = (uint32_t)(r0 + (lane & 15)) * RS + ((lane >> 4) << 4);
    const uint32_t brow = (lane & 7) + ((lane & 16) >> 1);
    const uint32_t bkof = (lane & 8) << 1;
#pragma unroll
    for (int ks = 0; ks < 8; ++ks) {
        const uint32_t kb = ks * 32;
        uint32_t ah0, ah1, ah2, ah3, al0, al1, al2, al3;
        ldsm4(ah0, ah1, ah2, ah3, ah_t + aoff + kb);
        ldsm4(al0, al1, al2, al3, al_t + aoff + kb);
#pragma unroll
        for (int np = 0; np < 4; ++np) {
            const uint32_t n0 = (uint32_t)(ntb + 2 * np) * 8;
            const uint32_t ba = (n0 + brow) * RS + bkof + kb;
            uint32_t bh0, bh1, bh2, bh3, bl0, bl1, bl2, bl3;
            ldsm4(bh0, bh1, bh2, bh3, wh + ba);
            ldsm4(bl0, bl1, bl2, bl3, wl + ba);
            mma16816(d[2 * np],     ah0, ah1, ah2, ah3, bh0, bh1);
            mma16816(d[2 * np],     al0, al1, al2, al3, bh0, bh1);
            mma16816(d[2 * np],     ah0, ah1, ah2, ah3, bl0, bl1);
            mma16816(d[2 * np + 1], ah0, ah1, ah2, ah3, bh2, bh3);
            mma16816(d[2 * np + 1], al0, al1, al2, al3, bh2, bh3);
            mma16816(d[2 * np + 1], ah0, ah1, ah2, ah3, bl2, bl3);
        }
    }
}

__device__ __forceinline__ void stage_w(char* sm, int m, int tid) {
    const uint4* s = (const uint4*)g_wimg[m];
    uint4* d = (uint4*)(sm + WHO);
#pragma unroll 2
    for (int i = tid; i < 4352; i += NT) d[i] = s[i];
}

__global__ __launch_bounds__(NT, 1)
void laa_mma_kernel(const float* __restrict__ x, const int* __restrict__ mask,
                    float* __restrict__ out)
{
    extern __shared__ __align__(16) char sm[];
    const uint32_t sb = smem_u32(sm);
    const int tid = threadIdx.x, lane = tid & 31, w = tid >> 5;
    const long long tok0 = (long long)blockIdx.x * TOKS;

    float* msk_f = (float*)(sm + MSK);
    float* rm_f  = (float*)(sm + RM);

    // ---- phase 0: X load + bf16 split; masks; stage Wq ----
#pragma unroll
    for (int it = 0; it < 8; ++it) {
        int idx = it * NT + tid;              // float4 index over [128][32]
        int row = idx >> 5, c4 = idx & 31;
        float4 v = __ldg((const float4*)x + (tok0 + row) * 32 + c4);
        __nv_bfloat16 hx = __float2bfloat16(v.x), hy = __float2bfloat16(v.y);
        __nv_bfloat16 hz = __float2bfloat16(v.z), hw = __float2bfloat16(v.w);
        uint2 hv, lv;
        hv.x = (uint32_t)__bfloat16_as_ushort(hx) | ((uint32_t)__bfloat16_as_ushort(hy) << 16);
        hv.y = (uint32_t)__bfloat16_as_ushort(hz) | ((uint32_t)__bfloat16_as_ushort(hw) << 16);
        lv.x = pkbf(v.x - __bfloat162float(hx), v.y - __bfloat162float(hy));
        lv.y = pkbf(v.z - __bfloat162float(hz), v.w - __bfloat162float(hw));
        *(uint2*)(sm + XH + row * RS + c4 * 8) = hv;
        *(uint2*)(sm + XL + row * RS + c4 * 8) = lv;
    }
    if (tid < TOKS) {
        msk_f[tid] = (__ldg(&mask[tok0 + tid]) != 0) ? 1.f : 0.f;
        long long b = tok0 + (tid & ~3);
        int any = __ldg(&mask[b]) | __ldg(&mask[b + 1]) | __ldg(&mask[b + 2]) | __ldg(&mask[b + 3]);
        rm_f[tid] = (any != 0) ? 1.f : 0.f;
    }
    stage_w(sm, 0, tid);
    __syncthreads();

    const int r0 = (w >> 1) * 16;
    const int ntb = (w & 1) * 8;
    const int ra = r0 + (lane >> 2), rb = ra + 8;

    // ---- GEMM Q -> QHO (fp16, bias+scale folded) ----
    {
        float d[8][4] = {};
        warp_gemm3(sb + XH, sb + XL, sb + WHO, sb + WLO, r0, ntb, d, lane);
#pragma unroll
        for (int j = 0; j < 8; ++j) {
            const int col = (ntb + j) * 8 + 2 * (lane & 3);
            const float b0 = g_bias[0][col], b1 = g_bias[0][col + 1];
            *(__half2*)(sm + QHO + ra * RS + col * 2) = __floats2half2_rn(d[j][0] + b0, d[j][1] + b1);
            *(__half2*)(sm + QHO + rb * RS + col * 2) = __floats2half2_rn(d[j][2] + b0, d[j][3] + b1);
        }
    }
    __syncthreads();
    stage_w(sm, 1, tid);
    __syncthreads();

    // ---- GEMM K -> KHO (fp16) ----
    {
        float d[8][4] = {};
        warp_gemm3(sb + XH, sb + XL, sb + WHO, sb + WLO, r0, ntb, d, lane);
#pragma unroll
        for (int j = 0; j < 8; ++j) {
            const int col = (ntb + j) * 8 + 2 * (lane & 3);
            const float b0 = g_bias[1][col], b1 = g_bias[1][col + 1];
            *(__half2*)(sm + KHO + ra * RS + col * 2) = __floats2half2_rn(d[j][0] + b0, d[j][1] + b1);
            *(__half2*)(sm + KHO + rb * RS + col * 2) = __floats2half2_rn(d[j][2] + b0, d[j][3] + b1);
        }
    }
    __syncthreads();
    stage_w(sm, 2, tid);
    __syncthreads();

    // ---- GEMM V; then overwrite dead X tiles with V (bf16 hi/lo) ----
    {
        float d[8][4] = {};
        warp_gemm3(sb + XH, sb + XL, sb + WHO, sb + WLO, r0, ntb, d, lane);
        __syncthreads();   // all ldmatrix reads of X done before overwrite
#pragma unroll
        for (int j = 0; j < 8; ++j) {
            const int col = (ntb + j) * 8 + 2 * (lane & 3);
            const float b0 = g_bias[2][col], b1 = g_bias[2][col + 1];
            float v0 = d[j][0] + b0, v1 = d[j][1] + b1;
            float v2 = d[j][2] + b0, v3 = d[j][3] + b1;
            __nv_bfloat16 h0 = __float2bfloat16(v0), h1 = __float2bfloat16(v1);
            __nv_bfloat16 h2 = __float2bfloat16(v2), h3 = __float2bfloat16(v3);
            *(uint32_t*)(sm + XH + ra * RS + col * 2) =
                (uint32_t)__bfloat16_as_ushort(h0) | ((uint32_t)__bfloat16_as_ushort(h1) << 16);
            *(uint32_t*)(sm + XL + ra * RS + col * 2) =
                pkbf(v0 - __bfloat162float(h0), v1 - __bfloat162float(h1));
            *(uint32_t*)(sm + XH + rb * RS + col * 2) =
                (uint32_t)__bfloat16_as_ushort(h2) | ((uint32_t)__bfloat16_as_ushort(h3) << 16);
            *(uint32_t*)(sm + XL + rb * RS + col * 2) =
                pkbf(v2 - __bfloat162float(h2), v3 - __bfloat162float(h3));
        }
    }
    __syncthreads();

    // ---- attention: one unit per thread (res, h, qa); y = P·v_head ----
    float y[32];
    int tq, hh;
    {
        const int res = tid >> 4;
        hh = (tid >> 2) & 3;
        const int qa = tid & 3;
        tq = res * 4 + qa;

        float q[32];
#pragma unroll
        for (int i = 0; i < 4; ++i) {
            uint4 u = *(const uint4*)(sm + QHO + tq * RS + hh * 64 + i * 16);
            float2 f0 = __half22float2(*(__half2*)&u.x);
            float2 f1 = __half22float2(*(__half2*)&u.y);
            float2 f2 = __half22float2(*(__half2*)&u.z);
            float2 f3 = __half22float2(*(__half2*)&u.w);
            q[i * 8 + 0] = f0.x; q[i * 8 + 1] = f0.y; q[i * 8 + 2] = f1.x; q[i * 8 + 3] = f1.y;
            q[i * 8 + 4] = f2.x; q[i * 8 + 5] = f2.y; q[i * 8 + 6] = f3.x; q[i * 8 + 7] = f3.y;
        }
        float s[4];
#pragma unroll
        for (int ka = 0; ka < 4; ++ka) {
            float acc = 0.f;
            const char* kp = sm + KHO + (res * 4 + ka) * RS + hh * 64;
#pragma unroll
            for (int i = 0; i < 4; ++i) {
                uint4 u = *(const uint4*)(kp + i * 16);
                float2 f0 = __half22float2(*(__half2*)&u.x);
                float2 f1 = __half22float2(*(__half2*)&u.y);
                float2 f2 = __half22float2(*(__half2*)&u.z);
                float2 f3 = __half22float2(*(__half2*)&u.w);
                acc = fmaf(q[i * 8 + 0], f0.x, acc); acc = fmaf(q[i * 8 + 1], f0.y, acc);
                acc = fmaf(q[i * 8 + 2], f1.x, acc); acc = fmaf(q[i * 8 + 3], f1.y, acc);
                acc = fmaf(q[i * 8 + 4], f2.x, acc); acc = fmaf(q[i * 8 + 5], f2.y, acc);
                acc = fmaf(q[i * 8 + 6], f3.x, acc); acc = fmaf(q[i * 8 + 7], f3.y, acc);
            }
            s[ka] = (msk_f[res * 4 + ka] != 0.f) ? acc : -1e30f;
        }
        const float mx = fmaxf(fmaxf(s[0], s[1]), fmaxf(s[2], s[3]));
        float p[4], ps = 0.f;
#pragma unroll
        for (int ka = 0; ka < 4; ++ka) { p[ka] = __expf(s[ka] - mx); ps += p[ka]; }
        const float inv = 1.f / ps;

#pragma unroll
        for (int d = 0; d < 32; ++d) y[d] = 0.f;
#pragma unroll
        for (int ka = 0; ka < 4; ++ka) {
            const float pw = p[ka] * inv;
            const char* vph = sm + XH + (res * 4 + ka) * RS + hh * 64;
            const char* vpl = sm + XL + (res * 4 + ka) * RS + hh * 64;
#pragma unroll
            for (int i = 0; i < 4; ++i) {
                uint4 uh = *(const uint4*)(vph + i * 16);
                uint4 ul = *(const uint4*)(vpl + i * 16);
                const uint32_t* hp = &uh.x;
                const uint32_t* lp = &ul.x;
#pragma unroll
                for (int g = 0; g < 4; ++g) {
                    float2 fh = __bfloat1622float2(*(__nv_bfloat162*)&hp[g]);
                    float2 fl = __bfloat1622float2(*(__nv_bfloat162*)&lp[g]);
                    y[i * 8 + g * 2 + 0] = fmaf(pw, fh.x + fl.x, y[i * 8 + g * 2 + 0]);
                    y[i * 8 + g * 2 + 1] = fmaf(pw, fh.y + fl.y, y[i * 8 + g * 2 + 1]);
                }
            }
        }
    }
    __syncthreads();   // all Q/K/V reads done before overwriting Q/K with Y

    // write Y: hi -> QHO tile, lo -> KHO tile; stage Wo in same phase
    {
#pragma unroll
        for (int i = 0; i < 4; ++i) {
            uint4 hv, lv;
            uint32_t* hp = &hv.x;
            uint32_t* lp = &lv.x;
#pragma unroll
            for (int g = 0; g < 4; ++g) {
                float a = y[i * 8 + g * 2], b = y[i * 8 + g * 2 + 1];
                __nv_bfloat16 ha = __float2bfloat16(a), hb = __float2bfloat16(b);
                hp[g] = (uint32_t)__bfloat16_as_ushort(ha) | ((uint32_t)__bfloat16_as_ushort(hb) << 16);
                lp[g] = pkbf(a - __bfloat162float(ha), b - __bfloat162float(hb));
            }
            *(uint4*)(sm + QHO + tq * RS + hh * 64 + i * 16) = hv;
            *(uint4*)(sm + KHO + tq * RS + hh * 64 + i * 16) = lv;
        }
    }
    stage_w(sm, 3, tid);
    __syncthreads();

    // ---- GEMM O: out = Y·Wo^T + bo, × residue mask ----
    {
        float d[8][4] = {};
        warp_gemm3(sb + QHO, sb + KHO, sb + WHO, sb + WLO, r0, ntb, d, lane);
        const float rma = rm_f[ra], rmb = rm_f[rb];
#pragma unroll
        for (int j = 0; j < 8; ++j) {
            const int col = (ntb + j) * 8 + 2 * (lane & 3);
            const float b0 = g_bias[3][col], b1 = g_bias[3][col + 1];
            float2 va, vb;
            va.x = (d[j][0] + b0) * rma; va.y = (d[j][1] + b1) * rma;
            vb.x = (d[j][2] + b0) * rmb; vb.y = (d[j][3] + b1) * rmb;
            *(float2*)(out + (tok0 + ra) * C + col) = va;
            *(float2*)(out + (tok0 + rb) * C + col) = vb;
        }
    }
}

extern "C" void kernel_launch(void* const* d_in, const int* in_sizes, int n_in,
                              void* d_out, int out_size)
{
    const float* x    = (const float*)d_in[0];
    const int*   mask = (const int*)d_in[1];
    const float* Wq = (const float*)d_in[2];
    const float* bq = (const float*)d_in[3];
    const float* Wk = (const float*)d_in[4];
    const float* bk = (const float*)d_in[5];
    const float* Wv = (const float*)d_in[6];
    const float* bv = (const float*)d_in[7];
    const float* Wo = (const float*)d_in[8];
    const float* bo = (const float*)d_in[9];
    float* out = (float*)d_out;

    const int ntok = in_sizes[0] / laa::C;      // 262144
    const int nblk = ntok / laa::TOKS;          // 2048

    prep_split<<<4, 256>>>(Wq, bq, Wk, bk, Wv, bv, Wo, bo);

    cudaFuncSetAttribute(laa_mma_kernel,
                         cudaFuncAttributeMaxDynamicSharedMemorySize, laa::TOTAL);
    laa_mma_kernel<<<nblk, laa::NT, laa::TOTAL>>>(x, mask, out);
}

// round 6
// speedup vs baseline: 3.9161x; 1.1948x over previous
#include <cuda_runtime.h>
#include <cuda_bf16.h>
#include <cuda_fp16.h>
#include <cstdint>

// LocalAtomAttention (round 6): mma.sync bf16x3, 64-token CTAs, 2 CTAs/SM.
// Q = x·(s·Wq)^T + s·bq (fp16 smem) ; K = x·Wk^T + bk (fp16 smem)
// V = x·Wv^T + bv (fp16, overwrites dead X-hi tile; halves held in regs)
// attention per (res, head, q_atom) thread -> Y (bf16 hi->QHO, lo->KHO)
// out = Y·Wo^T + bo, × residue mask.  W staged in N-halves via cp.async.

namespace laa {
constexpr int C = 128, TOKS = 64, NT = 256;
constexpr uint32_t RS = 272;            // smem row stride bytes
constexpr uint32_t XH = 0, XL = 17408, QHO = 34816, KHO = 52224,
                   WH = 69632, WL = 87040, MSK = 104448, RM = 104704,
                   TOTAL = 104960;      // x2 CTAs = 209,920 <= 228KB/SM
constexpr float SCALE = 0.17677669529663687f;  // 1/sqrt(32)
}

// Prepped weights: [4] = {Wq*s, Wk, Wv, Wo}, hi(34816B)+lo(34816B), 272B rows.
__device__ __align__(16) unsigned char g_wimg[4][69632];
__device__ float g_bias[4][128];   // {bq*s, bk, bv, bo}

// ---------------- helpers ----------------
__device__ __forceinline__ uint32_t smem_u32(const void* p) {
    uint32_t a;
    asm("{ .reg .u64 t; cvta.to.shared.u64 t, %1; cvt.u32.u64 %0, t; }" : "=r"(a) : "l"(p));
    return a;
}
__device__ __forceinline__ uint32_t pkbf(float a, float b) {
    __nv_bfloat162 t = __floats2bfloat162_rn(a, b);
    return *(uint32_t*)&t;
}
__device__ __forceinline__ void ldsm4(uint32_t& a0, uint32_t& a1, uint32_t& a2,
                                      uint32_t& a3, uint32_t addr) {
    asm volatile("ldmatrix.sync.aligned.m8n8.x4.shared.b16 {%0,%1,%2,%3}, [%4];"
                 : "=r"(a0), "=r"(a1), "=r"(a2), "=r"(a3) : "r"(addr));
}
__device__ __forceinline__ void mma16816(float d[4], uint32_t a0, uint32_t a1,
                                         uint32_t a2, uint32_t a3,
                                         uint32_t b0, uint32_t b1) {
    asm volatile(
        "mma.sync.aligned.m16n8k16.row.col.f32.bf16.bf16.f32 "
        "{%0,%1,%2,%3}, {%4,%5,%6,%7}, {%8,%9}, {%0,%1,%2,%3};"
        : "+f"(d[0]), "+f"(d[1]), "+f"(d[2]), "+f"(d[3])
        : "r"(a0), "r"(a1), "r"(a2), "r"(a3), "r"(b0), "r"(b1));
}
__device__ __forceinline__ void cpa16(uint32_t dst, const unsigned char* src) {
    uint64_t g;
    asm("cvta.to.global.u64 %0, %1;" : "=l"(g) : "l"(src));
    asm volatile("cp.async.cg.shared.global [%0], [%1], 16;" :: "r"(dst), "l"(g));
}
#define CPA_COMMIT() asm volatile("cp.async.commit_group;" ::: "memory")
#define CPA_WAIT0()  asm volatile("cp.async.wait_group 0;" ::: "memory")

// ---------------- prep kernel ----------------
__global__ void prep_split(const float* __restrict__ Wq, const float* __restrict__ bq,
                           const float* __restrict__ Wk, const float* __restrict__ bk,
                           const float* __restrict__ Wv, const float* __restrict__ bv,
                           const float* __restrict__ Wo, const float* __restrict__ bo) {
    int m = blockIdx.x;
    const float* src  = (m == 0) ? Wq : (m == 1) ? Wk : (m == 2) ? Wv : Wo;
    const float* bsrc = (m == 0) ? bq : (m == 1) ? bk : (m == 2) ? bv : bo;
    float sc = (m == 0) ? laa::SCALE : 1.f;
    unsigned char* img = g_wimg[m];
    for (int i = threadIdx.x; i < 16384; i += blockDim.x) {
        int row = i >> 7, col = i & 127;
        float f = src[i] * sc;
        __nv_bfloat16 h = __float2bfloat16(f);
        __nv_bfloat16 l = __float2bfloat16(f - __bfloat162float(h));
        *(__nv_bfloat16*)(img + row * laa::RS + col * 2) = h;
        *(__nv_bfloat16*)(img + 34816 + row * laa::RS + col * 2) = l;
    }
    if (threadIdx.x < 128) g_bias[m][threadIdx.x] = bsrc[threadIdx.x] * sc;
}

// ---------------- main kernel ----------------
using namespace laa;

// Warp GEMM: D[16 rows x 32 cols] += (Ah+Al)·(Bh+Bl)^T over K=128 (3-term).
__device__ __forceinline__ void warp_gemm3(uint32_t ah_t, uint32_t al_t,
                                           uint32_t wh, uint32_t wl,
                                           int r0, int nc0, float d[4][4], int lane) {
    const uint32_t aoff = (uint32_t)(r0 + (lane & 15)) * RS + ((lane >> 4) << 4);
    const uint32_t brow = (lane & 7) + ((lane & 16) >> 1);
    const uint32_t bkof = (lane & 8) << 1;
#pragma unroll
    for (int ks = 0; ks < 8; ++ks) {
        const uint32_t kb = ks * 32;
        uint32_t ah0, ah1, ah2, ah3, al0, al1, al2, al3;
        ldsm4(ah0, ah1, ah2, ah3, ah_t + aoff + kb);
        ldsm4(al0, al1, al2, al3, al_t + aoff + kb);
#pragma unroll
        for (int np = 0; np < 2; ++np) {
            const uint32_t ba = (uint32_t)(nc0 + np * 16 + brow) * RS + bkof + kb;
            uint32_t bh0, bh1, bh2, bh3, bl0, bl1, bl2, bl3;
            ldsm4(bh0, bh1, bh2, bh3, wh + ba);
            ldsm4(bl0, bl1, bl2, bl3, wl + ba);
            mma16816(d[2 * np],     ah0, ah1, ah2, ah3, bh0, bh1);
            mma16816(d[2 * np],     al0, al1, al2, al3, bh0, bh1);
            mma16816(d[2 * np],     ah0, ah1, ah2, ah3, bl0, bl1);
            mma16816(d[2 * np + 1], ah0, ah1, ah2, ah3, bh2, bh3);
            mma16816(d[2 * np + 1], al0, al1, al2, al3, bh2, bh3);
            mma16816(d[2 * np + 1], ah0, ah1, ah2, ah3, bl2, bl3);
        }
    }
}

// Stage N-half hf (64 out-channels) of matrix m into WH/WL via cp.async.
__device__ __forceinline__ void stage_w(uint32_t sb, int m, int hf, int tid) {
    const unsigned char* hi = g_wimg[m] + (uint32_t)hf * 17408;
    const unsigned char* lo = g_wimg[m] + 34816 + (uint32_t)hf * 17408;
    const uint32_t dh = sb + WH, dl = sb + WL;
#pragma unroll 2
    for (int i = tid; i < 1088; i += NT) {
        cpa16(dh + i * 16, hi + i * 16);
        cpa16(dl + i * 16, lo + i * 16);
    }
    CPA_COMMIT();
}

__global__ __launch_bounds__(NT, 2)
void laa_mma_kernel(const float* __restrict__ x, const int* __restrict__ mask,
                    float* __restrict__ out)
{
    extern __shared__ __align__(16) char sm[];
    const uint32_t sb = smem_u32(sm);
    const int tid = threadIdx.x, lane = tid & 31, w = tid >> 5;
    const long long tok0 = (long long)blockIdx.x * TOKS;

    float* msk_f = (float*)(sm + MSK);
    float* rm_f  = (float*)(sm + RM);

    // ---- P0: X load + bf16 split; masks; stage Wq half0 ----
    stage_w(sb, 0, 0, tid);
#pragma unroll
    for (int it = 0; it < 8; ++it) {
        int idx = it * NT + tid;              // float4 index over [64][32]
        int row = idx >> 5, c4 = idx & 31;
        float4 v = __ldg((const float4*)x + (tok0 + row) * 32 + c4);
        __nv_bfloat16 hx = __float2bfloat16(v.x), hy = __float2bfloat16(v.y);
        __nv_bfloat16 hz = __float2bfloat16(v.z), hw = __float2bfloat16(v.w);
        uint2 hv, lv;
        hv.x = (uint32_t)__bfloat16_as_ushort(hx) | ((uint32_t)__bfloat16_as_ushort(hy) << 16);
        hv.y = (uint32_t)__bfloat16_as_ushort(hz) | ((uint32_t)__bfloat16_as_ushort(hw) << 16);
        lv.x = pkbf(v.x - __bfloat162float(hx), v.y - __bfloat162float(hy));
        lv.y = pkbf(v.z - __bfloat162float(hz), v.w - __bfloat162float(hw));
        *(uint2*)(sm + XH + row * RS + c4 * 8) = hv;
        *(uint2*)(sm + XL + row * RS + c4 * 8) = lv;
    }
    if (tid < TOKS) {
        msk_f[tid] = (__ldg(&mask[tok0 + tid]) != 0) ? 1.f : 0.f;
        long long b = tok0 + (tid & ~3);
        int any = __ldg(&mask[b]) | __ldg(&mask[b + 1]) | __ldg(&mask[b + 2]) | __ldg(&mask[b + 3]);
        rm_f[tid] = (any != 0) ? 1.f : 0.f;
    }
    CPA_WAIT0();
    __syncthreads();

    const int r0 = (w >> 1) * 16;
    const int nc0 = (w & 1) * 32;
    const int ra = r0 + (lane >> 2), rb = ra + 8;
    const int c2 = 2 * (lane & 3);

    // ---- Q and K GEMMs (fp16 results, bias folded) ----
#pragma unroll
    for (int g = 0; g < 2; ++g) {                 // g=0: Q, g=1: K
        const uint32_t dsttile = (g == 0) ? QHO : KHO;
#pragma unroll
        for (int hf = 0; hf < 2; ++hf) {
            float d[4][4] = {};
            warp_gemm3(sb + XH, sb + XL, sb + WH, sb + WL, r0, nc0, d, lane);
#pragma unroll
            for (int j = 0; j < 4; ++j) {
                const int col = hf * 64 + nc0 + (j >> 1) * 16 + (j & 1) * 8 + c2;
                const float b0 = g_bias[g][col], b1 = g_bias[g][col + 1];
                *(__half2*)(sm + dsttile + ra * RS + col * 2) =
                    __floats2half2_rn(d[j][0] + b0, d[j][1] + b1);
                *(__half2*)(sm + dsttile + rb * RS + col * 2) =
                    __floats2half2_rn(d[j][2] + b0, d[j][3] + b1);
            }
            __syncthreads();
            // next stage: Q-h1, K-h0, K-h1, then V-h0
            const int nm = (g == 0) ? (hf == 0 ? 0 : 1) : (hf == 0 ? 1 : 2);
            const int nh = (hf == 0) ? 1 : 0;
            stage_w(sb, nm, nh, tid);
            CPA_WAIT0();
            __syncthreads();
        }
    }

    // ---- V GEMM: both halves into regs (X still live), then write fp16->XH ----
    float dv0[4][4] = {}, dv1[4][4] = {};
    warp_gemm3(sb + XH, sb + XL, sb + WH, sb + WL, r0, nc0, dv0, lane);
    __syncthreads();
    stage_w(sb, 2, 1, tid);
    CPA_WAIT0();
    __syncthreads();
    warp_gemm3(sb + XH, sb + XL, sb + WH, sb + WL, r0, nc0, dv1, lane);
    __syncthreads();   // all ldmatrix reads of X complete
#pragma unroll
    for (int hf = 0; hf < 2; ++hf) {
        float (*d)[4] = hf ? dv1 : dv0;
#pragma unroll
        for (int j = 0; j < 4; ++j) {
            const int col = hf * 64 + nc0 + (j >> 1) * 16 + (j & 1) * 8 + c2;
            const float b0 = g_bias[2][col], b1 = g_bias[2][col + 1];
            *(__half2*)(sm + XH + ra * RS + col * 2) =
                __floats2half2_rn(d[j][0] + b0, d[j][1] + b1);
            *(__half2*)(sm + XH + rb * RS + col * 2) =
                __floats2half2_rn(d[j][2] + b0, d[j][3] + b1);
        }
    }
    __syncthreads();

    // ---- attention: one unit per thread (res, h, qa); y = P·v_head ----
    float y[32];
    int tq, hh;
    {
        const int res = tid >> 4;
        hh = (tid >> 2) & 3;
        const int qa = tid & 3;
        tq = res * 4 + qa;

        float q[32];
#pragma unroll
        for (int i = 0; i < 4; ++i) {
            uint4 u = *(const uint4*)(sm + QHO + tq * RS + hh * 64 + i * 16);
            float2 f0 = __half22float2(*(__half2*)&u.x);
            float2 f1 = __half22float2(*(__half2*)&u.y);
            float2 f2 = __half22float2(*(__half2*)&u.z);
            float2 f3 = __half22float2(*(__half2*)&u.w);
            q[i * 8 + 0] = f0.x; q[i * 8 + 1] = f0.y; q[i * 8 + 2] = f1.x; q[i * 8 + 3] = f1.y;
            q[i * 8 + 4] = f2.x; q[i * 8 + 5] = f2.y; q[i * 8 + 6] = f3.x; q[i * 8 + 7] = f3.y;
        }
        float s[4];
#pragma unroll
        for (int ka = 0; ka < 4; ++ka) {
            float acc = 0.f;
            const char* kp = sm + KHO + (res * 4 + ka) * RS + hh * 64;
#pragma unroll
            for (int i = 0; i < 4; ++i) {
                uint4 u = *(const uint4*)(kp + i * 16);
                float2 f0 = __half22float2(*(__half2*)&u.x);
                float2 f1 = __half22float2(*(__half2*)&u.y);
                float2 f2 = __half22float2(*(__half2*)&u.z);
                float2 f3 = __half22float2(*(__half2*)&u.w);
                acc = fmaf(q[i * 8 + 0], f0.x, acc); acc = fmaf(q[i * 8 + 1], f0.y, acc);
                acc = fmaf(q[i * 8 + 2], f1.x, acc); acc = fmaf(q[i * 8 + 3], f1.y, acc);
                acc = fmaf(q[i * 8 + 4], f2.x, acc); acc = fmaf(q[i * 8 + 5], f2.y, acc);
                acc = fmaf(q[i * 8 + 6], f3.x, acc); acc = fmaf(q[i * 8 + 7], f3.y, acc);
            }
            s[ka] = (msk_f[res * 4 + ka] != 0.f) ? acc : -1e30f;
        }
        const float mx = fmaxf(fmaxf(s[0], s[1]), fmaxf(s[2], s[3]));
        float p[4], ps = 0.f;
#pragma unroll
        for (int ka = 0; ka < 4; ++ka) { p[ka] = __expf(s[ka] - mx); ps += p[ka]; }
        const float inv = 1.f / ps;

#pragma unroll
        for (int d = 0; d < 32; ++d) y[d] = 0.f;
#pragma unroll
        for (int ka = 0; ka < 4; ++ka) {
            const float pw = p[ka] * inv;
            const char* vp = sm + XH + (res * 4 + ka) * RS + hh * 64;
#pragma unroll
            for (int i = 0; i < 4; ++i) {
                uint4 u = *(const uint4*)(vp + i * 16);
                float2 f0 = __half22float2(*(__half2*)&u.x);
                float2 f1 = __half22float2(*(__half2*)&u.y);
                float2 f2 = __half22float2(*(__half2*)&u.z);
                float2 f3 = __half22float2(*(__half2*)&u.w);
                y[i * 8 + 0] = fmaf(pw, f0.x, y[i * 8 + 0]);
                y[i * 8 + 1] = fmaf(pw, f0.y, y[i * 8 + 1]);
                y[i * 8 + 2] = fmaf(pw, f1.x, y[i * 8 + 2]);
                y[i * 8 + 3] = fmaf(pw, f1.y, y[i * 8 + 3]);
                y[i * 8 + 4] = fmaf(pw, f2.x, y[i * 8 + 4]);
                y[i * 8 + 5] = fmaf(pw, f2.y, y[i * 8 + 5]);
                y[i * 8 + 6] = fmaf(pw, f3.x, y[i * 8 + 6]);
                y[i * 8 + 7] = fmaf(pw, f3.y, y[i * 8 + 7]);
            }
        }
    }
    __syncthreads();   // all Q/K/V reads done before overwriting Q/K with Y

    // write Y: hi(bf16) -> QHO, lo(bf16) -> KHO; stage Wo half0 same phase
    stage_w(sb, 3, 0, tid);
    {
#pragma unroll
        for (int i = 0; i < 4; ++i) {
            uint4 hv, lv;
            uint32_t* hp = &hv.x;
            uint32_t* lp = &lv.x;
#pragma unroll
            for (int gidx = 0; gidx < 4; ++gidx) {
                float a = y[i * 8 + gidx * 2], b = y[i * 8 + gidx * 2 + 1];
                __nv_bfloat16 ha = __float2bfloat16(a), hb = __float2bfloat16(b);
                hp[gidx] = (uint32_t)__bfloat16_as_ushort(ha) |
                           ((uint32_t)__bfloat16_as_ushort(hb) << 16);
                lp[gidx] = pkbf(a - __bfloat162float(ha), b - __bfloat162float(hb));
            }
            *(uint4*)(sm + QHO + tq * RS + hh * 64 + i * 16) = hv;
            *(uint4*)(sm + KHO + tq * RS + hh * 64 + i * 16) = lv;
        }
    }
    CPA_WAIT0();
    __syncthreads();

    // ---- O GEMM halves: out = Y·Wo^T + bo, × residue mask ----
    const float rma = rm_f[ra], rmb = rm_f[rb];
#pragma unroll
    for (int hf = 0; hf < 2; ++hf) {
        float d[4][4] = {};
        warp_gemm3(sb + QHO, sb + KHO, sb + WH, sb + WL, r0, nc0, d, lane);
#pragma unroll
        for (int j = 0; j < 4; ++j) {
            const int col = hf * 64 + nc0 + (j >> 1) * 16 + (j & 1) * 8 + c2;
            const float b0 = g_bias[3][col], b1 = g_bias[3][col + 1];
            float2 va, vb;
            va.x = (d[j][0] + b0) * rma; va.y = (d[j][1] + b1) * rma;
            vb.x = (d[j][2] + b0) * rmb; vb.y = (d[j][3] + b1) * rmb;
            *(float2*)(out + (tok0 + ra) * C + col) = va;
            *(float2*)(out + (tok0 + rb) * C + col) = vb;
        }
        if (hf == 0) {
            __syncthreads();
            stage_w(sb, 3, 1, tid);
            CPA_WAIT0();
            __syncthreads();
        }
    }
}

extern "C" void kernel_launch(void* const* d_in, const int* in_sizes, int n_in,
                              void* d_out, int out_size)
{
    const float* x    = (const float*)d_in[0];
    const int*   mask = (const int*)d_in[1];
    const float* Wq = (const float*)d_in[2];
    const float* bq = (const float*)d_in[3];
    const float* Wk = (const float*)d_in[4];
    const float* bk = (const float*)d_in[5];
    const float* Wv = (const float*)d_in[6];
    const float* bv = (const float*)d_in[7];
    const float* Wo = (const float*)d_in[8];
    const float* bo = (const float*)d_in[9];
    float* out = (float*)d_out;

    const int ntok = in_sizes[0] / laa::C;      // 262144
    const int nblk = ntok / laa::TOKS;          // 4096

    prep_split<<<4, 256>>>(Wq, bq, Wk, bk, Wv, bv, Wo, bo);

    cudaFuncSetAttribute(laa_mma_kernel,
                         cudaFuncAttributeMaxDynamicSharedMemorySize, laa::TOTAL);
    laa_mma_kernel<<<nblk, laa::NT, laa::TOTAL>>>(x, mask, out);
}

// round 7
// speedup vs baseline: 5.4628x; 1.3950x over previous
#include <cuda_runtime.h>
#include <cuda_fp16.h>
#include <cstdint>

// LocalAtomAttention (round 7): mma.sync fp16 2-term split, cp.async
// double-buffered W prefetch, 64-token CTAs, 2 CTAs/SM.
// x = xh + xl (both fp16, exact to 2^-22); per GEMM: (xh+xl)·fp16(W) via two
// f16 MMAs per fragment pair (drops only x·wl ~ 2^-11 rel).
// Q = x·(s·Wq)^T + s·bq (fp16 smem) ; K = x·Wk^T + bk (fp16 smem)
// V = x·Wv^T + bv (fp16, overwrites dead XH tile)
// attention per (res, head, q_atom) thread -> Y (fp16 hi->QHO, lo->KHO)
// out = Y·Wo^T + bo, × residue mask.

namespace laa {
constexpr int C = 128, TOKS = 64, NT = 256;
constexpr uint32_t RS = 272;            // smem row stride bytes
constexpr uint32_t XH = 0, XL = 17408, QHO = 34816, KHO = 52224,
                   WA = 69632, WB = 87040, MSK = 104448, RM = 104704,
                   TOTAL = 104960;      // x2 CTAs = 209,920 <= 228KB/SM
constexpr float SCALE = 0.17677669529663687f;  // 1/sqrt(32)
}

// Prepped fp16 weights: [4] = {Wq*s, Wk, Wv, Wo}, 272B rows, 34816B each.
__device__ __align__(16) unsigned char g_wimg[4][34816];
__device__ float g_bias[4][128];   // {bq*s, bk, bv, bo}

// ---------------- helpers ----------------
__device__ __forceinline__ uint32_t smem_u32(const void* p) {
    uint32_t a;
    asm("{ .reg .u64 t; cvta.to.shared.u64 t, %1; cvt.u32.u64 %0, t; }" : "=r"(a) : "l"(p));
    return a;
}
__device__ __forceinline__ void ldsm4(uint32_t& a0, uint32_t& a1, uint32_t& a2,
                                      uint32_t& a3, uint32_t addr) {
    asm volatile("ldmatrix.sync.aligned.m8n8.x4.shared.b16 {%0,%1,%2,%3}, [%4];"
                 : "=r"(a0), "=r"(a1), "=r"(a2), "=r"(a3) : "r"(addr));
}
__device__ __forceinline__ void mma16816(float d[4], uint32_t a0, uint32_t a1,
                                         uint32_t a2, uint32_t a3,
                                         uint32_t b0, uint32_t b1) {
    asm volatile(
        "mma.sync.aligned.m16n8k16.row.col.f32.f16.f16.f32 "
        "{%0,%1,%2,%3}, {%4,%5,%6,%7}, {%8,%9}, {%0,%1,%2,%3};"
        : "+f"(d[0]), "+f"(d[1]), "+f"(d[2]), "+f"(d[3])
        : "r"(a0), "r"(a1), "r"(a2), "r"(a3), "r"(b0), "r"(b1));
}
__device__ __forceinline__ void cpa16(uint32_t dst, const unsigned char* src) {
    uint64_t g;
    asm("cvta.to.global.u64 %0, %1;" : "=l"(g) : "l"(src));
    asm volatile("cp.async.cg.shared.global [%0], [%1], 16;" :: "r"(dst), "l"(g));
}
#define CPA_COMMIT() asm volatile("cp.async.commit_group;" ::: "memory")
#define CPA_WAIT0()  asm volatile("cp.async.wait_group 0;" ::: "memory")

// ---------------- prep kernel ----------------
__global__ void prep_split(const float* __restrict__ Wq, const float* __restrict__ bq,
                           const float* __restrict__ Wk, const float* __restrict__ bk,
                           const float* __restrict__ Wv, const float* __restrict__ bv,
                           const float* __restrict__ Wo, const float* __restrict__ bo) {
    int m = blockIdx.x;
    const float* src  = (m == 0) ? Wq : (m == 1) ? Wk : (m == 2) ? Wv : Wo;
    const float* bsrc = (m == 0) ? bq : (m == 1) ? bk : (m == 2) ? bv : bo;
    float sc = (m == 0) ? laa::SCALE : 1.f;
    unsigned char* img = g_wimg[m];
    for (int i = threadIdx.x; i < 16384; i += blockDim.x) {
        int row = i >> 7, col = i & 127;
        *(__half*)(img + row * laa::RS + col * 2) = __float2half_rn(src[i] * sc);
    }
    if (threadIdx.x < 128) g_bias[m][threadIdx.x] = bsrc[threadIdx.x] * sc;
}

// ---------------- main kernel ----------------
using namespace laa;

// Warp GEMM: D[16 rows x 32 cols] += (Ah+Al)·B^T over K=128 (2-term fp16).
__device__ __forceinline__ void warp_gemm2(uint32_t ah_t, uint32_t al_t,
                                           uint32_t wbuf,
                                           int r0, int nc0, float d[4][4], int lane) {
    const uint32_t aoff = (uint32_t)(r0 + (lane & 15)) * RS + ((lane >> 4) << 4);
    const uint32_t brow = (lane & 7) + ((lane & 16) >> 1);
    const uint32_t bkof = (lane & 8) << 1;
#pragma unroll
    for (int ks = 0; ks < 8; ++ks) {
        const uint32_t kb = ks * 32;
        uint32_t ah0, ah1, ah2, ah3, al0, al1, al2, al3;
        ldsm4(ah0, ah1, ah2, ah3, ah_t + aoff + kb);
        ldsm4(al0, al1, al2, al3, al_t + aoff + kb);
#pragma unroll
        for (int np = 0; np < 2; ++np) {
            const uint32_t ba = (uint32_t)(nc0 + np * 16 + brow) * RS + bkof + kb;
            uint32_t b0, b1, b2, b3;
            ldsm4(b0, b1, b2, b3, wbuf + ba);
            mma16816(d[2 * np],     ah0, ah1, ah2, ah3, b0, b1);
            mma16816(d[2 * np],     al0, al1, al2, al3, b0, b1);
            mma16816(d[2 * np + 1], ah0, ah1, ah2, ah3, b2, b3);
            mma16816(d[2 * np + 1], al0, al1, al2, al3, b2, b3);
        }
    }
}

// Issue cp.async stage of W half hf (64 out-channels) of matrix m into dst.
__device__ __forceinline__ void stage_w(uint32_t dst, int m, int hf, int tid) {
    const unsigned char* src = g_wimg[m] + (uint32_t)hf * 17408;
#pragma unroll 2
    for (int i = tid; i < 1088; i += NT) cpa16(dst + i * 16, src + i * 16);
    CPA_COMMIT();
}

__global__ __launch_bounds__(NT, 2)
void laa_mma_kernel(const float* __restrict__ x, const int* __restrict__ mask,
                    float* __restrict__ out)
{
    extern __shared__ __align__(16) char sm[];
    const uint32_t sb = smem_u32(sm);
    const int tid = threadIdx.x, lane = tid & 31, w = tid >> 5;
    const long long tok0 = (long long)blockIdx.x * TOKS;

    float* msk_f = (float*)(sm + MSK);
    float* rm_f  = (float*)(sm + RM);

    // ---- P-1: issue Wq-h0 -> WA; X load + fp16 split; masks ----
    stage_w(sb + WA, 0, 0, tid);
#pragma unroll
    for (int it = 0; it < 8; ++it) {
        int idx = it * NT + tid;              // float4 index over [64][32]
        int row = idx >> 5, c4 = idx & 31;
        float4 v = __ldg((const float4*)x + (tok0 + row) * 32 + c4);
        __half2 h01 = __floats2half2_rn(v.x, v.y);
        __half2 h23 = __floats2half2_rn(v.z, v.w);
        float2 f01 = __half22float2(h01), f23 = __half22float2(h23);
        __half2 l01 = __floats2half2_rn(v.x - f01.x, v.y - f01.y);
        __half2 l23 = __floats2half2_rn(v.z - f23.x, v.w - f23.y);
        uint2 hv, lv;
        hv.x = *(uint32_t*)&h01; hv.y = *(uint32_t*)&h23;
        lv.x = *(uint32_t*)&l01; lv.y = *(uint32_t*)&l23;
        *(uint2*)(sm + XH + row * RS + c4 * 8) = hv;
        *(uint2*)(sm + XL + row * RS + c4 * 8) = lv;
    }
    if (tid < TOKS) {
        msk_f[tid] = (__ldg(&mask[tok0 + tid]) != 0) ? 1.f : 0.f;
        long long b = tok0 + (tid & ~3);
        int any = __ldg(&mask[b]) | __ldg(&mask[b + 1]) | __ldg(&mask[b + 2]) | __ldg(&mask[b + 3]);
        rm_f[tid] = (any != 0) ? 1.f : 0.f;
    }
    CPA_WAIT0();
    __syncthreads();

    const int r0 = (w >> 1) * 16;
    const int nc0 = (w & 1) * 32;
    const int ra = r0 + (lane >> 2), rb = ra + 8;
    const int c2 = 2 * (lane & 3);

    // ---- P0-P3: Q and K GEMMs, double-buffered W prefetch ----
    // stage sequence s: 0:Wq0 1:Wq1 2:Wk0 3:Wk1 4:Wv0 5:Wv1 6:Wo0 7:Wo1
#pragma unroll
    for (int g = 0; g < 2; ++g) {                 // g=0: Q, g=1: K
        const uint32_t dsttile = (g == 0) ? QHO : KHO;
#pragma unroll
        for (int hf = 0; hf < 2; ++hf) {
            const int ph = g * 2 + hf;
            const uint32_t cur = (ph & 1) ? WB : WA;
            const uint32_t nxt = (ph & 1) ? WA : WB;
            stage_w(sb + nxt, (ph + 1) >> 1, (ph + 1) & 1, tid);  // prefetch next
            float d[4][4] = {};
            warp_gemm2(sb + XH, sb + XL, sb + cur, r0, nc0, d, lane);
#pragma unroll
            for (int j = 0; j < 4; ++j) {
                const int col = hf * 64 + nc0 + (j >> 1) * 16 + (j & 1) * 8 + c2;
                const float b0 = g_bias[g][col], b1 = g_bias[g][col + 1];
                *(__half2*)(sm + dsttile + ra * RS + col * 2) =
                    __floats2half2_rn(d[j][0] + b0, d[j][1] + b1);
                *(__half2*)(sm + dsttile + rb * RS + col * 2) =
                    __floats2half2_rn(d[j][2] + b0, d[j][3] + b1);
            }
            CPA_WAIT0();
            __syncthreads();
        }
    }

    // ---- P4: V-h0 from WA -> dv0; prefetch Wv-h1 -> WB ----
    float dv0[4][4] = {}, dv1[4][4] = {};
    stage_w(sb + WB, 2, 1, tid);
    warp_gemm2(sb + XH, sb + XL, sb + WA, r0, nc0, dv0, lane);
    CPA_WAIT0();
    __syncthreads();

    // ---- P5: V-h1 from WB -> dv1; prefetch Wo-h0 -> WA ----
    stage_w(sb + WA, 3, 0, tid);
    warp_gemm2(sb + XH, sb + XL, sb + WB, r0, nc0, dv1, lane);
    CPA_WAIT0();
    __syncthreads();   // all ldmatrix reads of X complete

    // ---- P6: prefetch Wo-h1 -> WB; write V (fp16) into dead XH ----
    stage_w(sb + WB, 3, 1, tid);
#pragma unroll
    for (int hf = 0; hf < 2; ++hf) {
        float (*d)[4] = hf ? dv1 : dv0;
#pragma unroll
        for (int j = 0; j < 4; ++j) {
            const int col = hf * 64 + nc0 + (j >> 1) * 16 + (j & 1) * 8 + c2;
            const float b0 = g_bias[2][col], b1 = g_bias[2][col + 1];
            *(__half2*)(sm + XH + ra * RS + col * 2) =
                __floats2half2_rn(d[j][0] + b0, d[j][1] + b1);
            *(__half2*)(sm + XH + rb * RS + col * 2) =
                __floats2half2_rn(d[j][2] + b0, d[j][3] + b1);
        }
    }
    CPA_WAIT0();
    __syncthreads();

    // ---- P7: attention, one unit per thread (res, h, qa); y = P·v_head ----
    float y[32];
    int tq, hh;
    {
        const int res = tid >> 4;
        hh = (tid >> 2) & 3;
        const int qa = tid & 3;
        tq = res * 4 + qa;

        float q[32];
#pragma unroll
        for (int i = 0; i < 4; ++i) {
            uint4 u = *(const uint4*)(sm + QHO + tq * RS + hh * 64 + i * 16);
            float2 f0 = __half22float2(*(__half2*)&u.x);
            float2 f1 = __half22float2(*(__half2*)&u.y);
            float2 f2 = __half22float2(*(__half2*)&u.z);
            float2 f3 = __half22float2(*(__half2*)&u.w);
            q[i * 8 + 0] = f0.x; q[i * 8 + 1] = f0.y; q[i * 8 + 2] = f1.x; q[i * 8 + 3] = f1.y;
            q[i * 8 + 4] = f2.x; q[i * 8 + 5] = f2.y; q[i * 8 + 6] = f3.x; q[i * 8 + 7] = f3.y;
        }
        float s[4];
#pragma unroll
        for (int ka = 0; ka < 4; ++ka) {
            float acc = 0.f;
            const char* kp = sm + KHO + (res * 4 + ka) * RS + hh * 64;
#pragma unroll
            for (int i = 0; i < 4; ++i) {
                uint4 u = *(const uint4*)(kp + i * 16);
                float2 f0 = __half22float2(*(__half2*)&u.x);
                float2 f1 = __half22float2(*(__half2*)&u.y);
                float2 f2 = __half22float2(*(__half2*)&u.z);
                float2 f3 = __half22float2(*(__half2*)&u.w);
                acc = fmaf(q[i * 8 + 0], f0.x, acc); acc = fmaf(q[i * 8 + 1], f0.y, acc);
                acc = fmaf(q[i * 8 + 2], f1.x, acc); acc = fmaf(q[i * 8 + 3], f1.y, acc);
                acc = fmaf(q[i * 8 + 4], f2.x, acc); acc = fmaf(q[i * 8 + 5], f2.y, acc);
                acc = fmaf(q[i * 8 + 6], f3.x, acc); acc = fmaf(q[i * 8 + 7], f3.y, acc);
            }
            s[ka] = (msk_f[res * 4 + ka] != 0.f) ? acc : -1e30f;
        }
        const float mx = fmaxf(fmaxf(s[0], s[1]), fmaxf(s[2], s[3]));
        float p[4], ps = 0.f;
#pragma unroll
        for (int ka = 0; ka < 4; ++ka) { p[ka] = __expf(s[ka] - mx); ps += p[ka]; }
        const float inv = 1.f / ps;

#pragma unroll
        for (int d = 0; d < 32; ++d) y[d] = 0.f;
#pragma unroll
        for (int ka = 0; ka < 4; ++ka) {
            const float pw = p[ka] * inv;
            const char* vp = sm + XH + (res * 4 + ka) * RS + hh * 64;
#pragma unroll
            for (int i = 0; i < 4; ++i) {
                uint4 u = *(const uint4*)(vp + i * 16);
                float2 f0 = __half22float2(*(__half2*)&u.x);
                float2 f1 = __half22float2(*(__half2*)&u.y);
                float2 f2 = __half22float2(*(__half2*)&u.z);
                float2 f3 = __half22float2(*(__half2*)&u.w);
                y[i * 8 + 0] = fmaf(pw, f0.x, y[i * 8 + 0]);
                y[i * 8 + 1] = fmaf(pw, f0.y, y[i * 8 + 1]);
                y[i * 8 + 2] = fmaf(pw, f1.x, y[i * 8 + 2]);
                y[i * 8 + 3] = fmaf(pw, f1.y, y[i * 8 + 3]);
                y[i * 8 + 4] = fmaf(pw, f2.x, y[i * 8 + 4]);
                y[i * 8 + 5] = fmaf(pw, f2.y, y[i * 8 + 5]);
                y[i * 8 + 6] = fmaf(pw, f3.x, y[i * 8 + 6]);
                y[i * 8 + 7] = fmaf(pw, f3.y, y[i * 8 + 7]);
            }
        }
    }
    __syncthreads();   // all Q/K/V reads done before overwriting Q/K with Y

    // ---- P8: write Y fp16 split: hi -> QHO, lo -> KHO ----
    {
#pragma unroll
        for (int i = 0; i < 4; ++i) {
            uint4 hv, lv;
            uint32_t* hp = &hv.x;
            uint32_t* lp = &lv.x;
#pragma unroll
            for (int gidx = 0; gidx < 4; ++gidx) {
                float a = y[i * 8 + gidx * 2], b = y[i * 8 + gidx * 2 + 1];
                __half2 h = __floats2half2_rn(a, b);
                float2 f = __half22float2(h);
                __half2 l = __floats2half2_rn(a - f.x, b - f.y);
                hp[gidx] = *(uint32_t*)&h;
                lp[gidx] = *(uint32_t*)&l;
            }
            *(uint4*)(sm + QHO + tq * RS + hh * 64 + i * 16) = hv;
            *(uint4*)(sm + KHO + tq * RS + hh * 64 + i * 16) = lv;
        }
    }
    __syncthreads();

    // ---- P9: O GEMM halves (Wo-h0 in WA, Wo-h1 in WB): out = Y·Wo^T + bo ----
    const float rma = rm_f[ra], rmb = rm_f[rb];
#pragma unroll
    for (int hf = 0; hf < 2; ++hf) {
        const uint32_t cur = hf ? WB : WA;
        float d[4][4] = {};
        warp_gemm2(sb + QHO, sb + KHO, sb + cur, r0, nc0, d, lane);
#pragma unroll
        for (int j = 0; j < 4; ++j) {
            const int col = hf * 64 + nc0 + (j >> 1) * 16 + (j & 1) * 8 + c2;
            const float b0 = g_bias[3][col], b1 = g_bias[3][col + 1];
            float2 va, vb;
            va.x = (d[j][0] + b0) * rma; va.y = (d[j][1] + b1) * rma;
            vb.x = (d[j][2] + b0) * rmb; vb.y = (d[j][3] + b1) * rmb;
            *(float2*)(out + (tok0 + ra) * C + col) = va;
            *(float2*)(out + (tok0 + rb) * C + col) = vb;
        }
    }
}

extern "C" void kernel_launch(void* const* d_in, const int* in_sizes, int n_in,
                              void* d_out, int out_size)
{
    const float* x    = (const float*)d_in[0];
    const int*   mask = (const int*)d_in[1];
    const float* Wq = (const float*)d_in[2];
    const float* bq = (const float*)d_in[3];
    const float* Wk = (const float*)d_in[4];
    const float* bk = (const float*)d_in[5];
    const float* Wv = (const float*)d_in[6];
    const float* bv = (const float*)d_in[7];
    const float* Wo = (const float*)d_in[8];
    const float* bo = (const float*)d_in[9];
    float* out = (float*)d_out;

    const int ntok = in_sizes[0] / laa::C;      // 262144
    const int nblk = ntok / laa::TOKS;          // 4096

    prep_split<<<4, 256>>>(Wq, bq, Wk, bk, Wv, bv, Wo, bo);

    cudaFuncSetAttribute(laa_mma_kernel,
                         cudaFuncAttributeMaxDynamicSharedMemorySize, laa::TOTAL);
    laa_mma_kernel<<<nblk, laa::NT, laa::TOTAL>>>(x, mask, out);
}

// round 8
// speedup vs baseline: 6.8362x; 1.2514x over previous
#include <cuda_runtime.h>
#include <cuda_fp16.h>
#include <cstdint>

// LocalAtomAttention (round 8): mma.sync fp16 1-term, cp.async double-buffered
// W prefetch, 64-token CTAs, 2 CTAs/SM.
// x stored fp16 (1-term); per GEMM: fp16(x)·fp16(W), fp32 accumulate.
// Q = x·(s·Wq)^T + s·bq (fp16 smem) ; K = x·Wk^T + bk (fp16 smem)
// V = x·Wv^T + bv (fp16, overwrites dead XH tile)
// attention per (res, head, q_atom) thread -> Y (fp16 -> QHO tile)
// out = Y·Wo^T + bo, × residue mask.

namespace laa {
constexpr int C = 128, TOKS = 64, NT = 256;
constexpr uint32_t RS = 272;            // smem row stride bytes
constexpr uint32_t XH = 0, QHO = 17408, KHO = 34816,
                   WA = 52224, WB = 69632, MSK = 87040, RM = 87296,
                   TOTAL = 87552;       // x2 CTAs = 175,104 <= 228KB/SM
constexpr float SCALE = 0.17677669529663687f;  // 1/sqrt(32)
}

// Prepped fp16 weights: [4] = {Wq*s, Wk, Wv, Wo}, 272B rows, 34816B each.
__device__ __align__(16) unsigned char g_wimg[4][34816];
__device__ float g_bias[4][128];   // {bq*s, bk, bv, bo}

// ---------------- helpers ----------------
__device__ __forceinline__ uint32_t smem_u32(const void* p) {
    uint32_t a;
    asm("{ .reg .u64 t; cvta.to.shared.u64 t, %1; cvt.u32.u64 %0, t; }" : "=r"(a) : "l"(p));
    return a;
}
__device__ __forceinline__ void ldsm4(uint32_t& a0, uint32_t& a1, uint32_t& a2,
                                      uint32_t& a3, uint32_t addr) {
    asm volatile("ldmatrix.sync.aligned.m8n8.x4.shared.b16 {%0,%1,%2,%3}, [%4];"
                 : "=r"(a0), "=r"(a1), "=r"(a2), "=r"(a3) : "r"(addr));
}
__device__ __forceinline__ void mma16816(float d[4], uint32_t a0, uint32_t a1,
                                         uint32_t a2, uint32_t a3,
                                         uint32_t b0, uint32_t b1) {
    asm volatile(
        "mma.sync.aligned.m16n8k16.row.col.f32.f16.f16.f32 "
        "{%0,%1,%2,%3}, {%4,%5,%6,%7}, {%8,%9}, {%0,%1,%2,%3};"
        : "+f"(d[0]), "+f"(d[1]), "+f"(d[2]), "+f"(d[3])
        : "r"(a0), "r"(a1), "r"(a2), "r"(a3), "r"(b0), "r"(b1));
}
__device__ __forceinline__ void cpa16(uint32_t dst, const unsigned char* src) {
    uint64_t g;
    asm("cvta.to.global.u64 %0, %1;" : "=l"(g) : "l"(src));
    asm volatile("cp.async.cg.shared.global [%0], [%1], 16;" :: "r"(dst), "l"(g));
}
#define CPA_COMMIT() asm volatile("cp.async.commit_group;" ::: "memory")
#define CPA_WAIT0()  asm volatile("cp.async.wait_group 0;" ::: "memory")

// ---------------- prep kernel ----------------
__global__ void prep_split(const float* __restrict__ Wq, const float* __restrict__ bq,
                           const float* __restrict__ Wk, const float* __restrict__ bk,
                           const float* __restrict__ Wv, const float* __restrict__ bv,
                           const float* __restrict__ Wo, const float* __restrict__ bo) {
    int m = blockIdx.x;
    const float* src  = (m == 0) ? Wq : (m == 1) ? Wk : (m == 2) ? Wv : Wo;
    const float* bsrc = (m == 0) ? bq : (m == 1) ? bk : (m == 2) ? bv : bo;
    float sc = (m == 0) ? laa::SCALE : 1.f;
    unsigned char* img = g_wimg[m];
    for (int i = threadIdx.x; i < 16384; i += blockDim.x) {
        int row = i >> 7, col = i & 127;
        *(__half*)(img + row * laa::RS + col * 2) = __float2half_rn(src[i] * sc);
    }
    if (threadIdx.x < 128) g_bias[m][threadIdx.x] = bsrc[threadIdx.x] * sc;
}

// ---------------- main kernel ----------------
using namespace laa;

// Warp GEMM: D[16 rows x 32 cols] += A·B^T over K=128 (fp16 operands).
__device__ __forceinline__ void warp_gemm1(uint32_t a_t, uint32_t wbuf,
                                           int r0, int nc0, float d[4][4], int lane) {
    const uint32_t aoff = (uint32_t)(r0 + (lane & 15)) * RS + ((lane >> 4) << 4);
    const uint32_t brow = (lane & 7) + ((lane & 16) >> 1);
    const uint32_t bkof = (lane & 8) << 1;
#pragma unroll
    for (int ks = 0; ks < 8; ++ks) {
        const uint32_t kb = ks * 32;
        uint32_t a0, a1, a2, a3;
        ldsm4(a0, a1, a2, a3, a_t + aoff + kb);
#pragma unroll
        for (int np = 0; np < 2; ++np) {
            const uint32_t ba = (uint32_t)(nc0 + np * 16 + brow) * RS + bkof + kb;
            uint32_t b0, b1, b2, b3;
            ldsm4(b0, b1, b2, b3, wbuf + ba);
            mma16816(d[2 * np],     a0, a1, a2, a3, b0, b1);
            mma16816(d[2 * np + 1], a0, a1, a2, a3, b2, b3);
        }
    }
}

// Issue cp.async stage of W half hf (64 out-channels) of matrix m into dst.
__device__ __forceinline__ void stage_w(uint32_t dst, int m, int hf, int tid) {
    const unsigned char* src = g_wimg[m] + (uint32_t)hf * 17408;
#pragma unroll 2
    for (int i = tid; i < 1088; i += NT) cpa16(dst + i * 16, src + i * 16);
    CPA_COMMIT();
}

__global__ __launch_bounds__(NT, 2)
void laa_mma_kernel(const float* __restrict__ x, const int* __restrict__ mask,
                    float* __restrict__ out)
{
    extern __shared__ __align__(16) char sm[];
    const uint32_t sb = smem_u32(sm);
    const int tid = threadIdx.x, lane = tid & 31, w = tid >> 5;
    const long long tok0 = (long long)blockIdx.x * TOKS;

    float* msk_f = (float*)(sm + MSK);
    float* rm_f  = (float*)(sm + RM);

    // ---- P-1: issue Wq-h0 -> WA; X load + fp16 convert; masks ----
    stage_w(sb + WA, 0, 0, tid);
#pragma unroll
    for (int it = 0; it < 8; ++it) {
        int idx = it * NT + tid;              // float4 index over [64][32]
        int row = idx >> 5, c4 = idx & 31;
        float4 v = __ldg((const float4*)x + (tok0 + row) * 32 + c4);
        __half2 h01 = __floats2half2_rn(v.x, v.y);
        __half2 h23 = __floats2half2_rn(v.z, v.w);
        uint2 hv;
        hv.x = *(uint32_t*)&h01; hv.y = *(uint32_t*)&h23;
        *(uint2*)(sm + XH + row * RS + c4 * 8) = hv;
    }
    if (tid < TOKS) {
        msk_f[tid] = (__ldg(&mask[tok0 + tid]) != 0) ? 1.f : 0.f;
        long long b = tok0 + (tid & ~3);
        int any = __ldg(&mask[b]) | __ldg(&mask[b + 1]) | __ldg(&mask[b + 2]) | __ldg(&mask[b + 3]);
        rm_f[tid] = (any != 0) ? 1.f : 0.f;
    }
    CPA_WAIT0();
    __syncthreads();

    const int r0 = (w >> 1) * 16;
    const int nc0 = (w & 1) * 32;
    const int ra = r0 + (lane >> 2), rb = ra + 8;
    const int c2 = 2 * (lane & 3);

    // ---- P0-P3: Q and K GEMMs, double-buffered W prefetch ----
    // stage sequence: 0:Wq0 1:Wq1 2:Wk0 3:Wk1 4:Wv0 5:Wv1 6:Wo0 7:Wo1
#pragma unroll
    for (int g = 0; g < 2; ++g) {                 // g=0: Q, g=1: K
        const uint32_t dsttile = (g == 0) ? QHO : KHO;
#pragma unroll
        for (int hf = 0; hf < 2; ++hf) {
            const int ph = g * 2 + hf;
            const uint32_t cur = (ph & 1) ? WB : WA;
            const uint32_t nxt = (ph & 1) ? WA : WB;
            stage_w(sb + nxt, (ph + 1) >> 1, (ph + 1) & 1, tid);  // prefetch next
            float d[4][4] = {};
            warp_gemm1(sb + XH, sb + cur, r0, nc0, d, lane);
#pragma unroll
            for (int j = 0; j < 4; ++j) {
                const int col = hf * 64 + nc0 + (j >> 1) * 16 + (j & 1) * 8 + c2;
                const float b0 = g_bias[g][col], b1 = g_bias[g][col + 1];
                *(__half2*)(sm + dsttile + ra * RS + col * 2) =
                    __floats2half2_rn(d[j][0] + b0, d[j][1] + b1);
                *(__half2*)(sm + dsttile + rb * RS + col * 2) =
                    __floats2half2_rn(d[j][2] + b0, d[j][3] + b1);
            }
            CPA_WAIT0();
            __syncthreads();
        }
    }

    // ---- P4: V-h0 from WA -> dv0; prefetch Wv-h1 -> WB ----
    float dv0[4][4] = {}, dv1[4][4] = {};
    stage_w(sb + WB, 2, 1, tid);
    warp_gemm1(sb + XH, sb + WA, r0, nc0, dv0, lane);
    CPA_WAIT0();
    __syncthreads();

    // ---- P5: V-h1 from WB -> dv1; prefetch Wo-h0 -> WA ----
    stage_w(sb + WA, 3, 0, tid);
    warp_gemm1(sb + XH, sb + WB, r0, nc0, dv1, lane);
    CPA_WAIT0();
    __syncthreads();   // all ldmatrix reads of X complete

    // ---- P6: prefetch Wo-h1 -> WB; write V (fp16) into dead XH ----
    stage_w(sb + WB, 3, 1, tid);
#pragma unroll
    for (int hf = 0; hf < 2; ++hf) {
        float (*d)[4] = hf ? dv1 : dv0;
#pragma unroll
        for (int j = 0; j < 4; ++j) {
            const int col = hf * 64 + nc0 + (j >> 1) * 16 + (j & 1) * 8 + c2;
            const float b0 = g_bias[2][col], b1 = g_bias[2][col + 1];
            *(__half2*)(sm + XH + ra * RS + col * 2) =
                __floats2half2_rn(d[j][0] + b0, d[j][1] + b1);
            *(__half2*)(sm + XH + rb * RS + col * 2) =
                __floats2half2_rn(d[j][2] + b0, d[j][3] + b1);
        }
    }
    CPA_WAIT0();
    __syncthreads();

    // ---- P7: attention, one unit per thread (res, h, qa); y = P·v_head ----
    float y[32];
    int tq, hh;
    {
        const int res = tid >> 4;
        hh = (tid >> 2) & 3;
        const int qa = tid & 3;
        tq = res * 4 + qa;

        float q[32];
#pragma unroll
        for (int i = 0; i < 4; ++i) {
            uint4 u = *(const uint4*)(sm + QHO + tq * RS + hh * 64 + i * 16);
            float2 f0 = __half22float2(*(__half2*)&u.x);
            float2 f1 = __half22float2(*(__half2*)&u.y);
            float2 f2 = __half22float2(*(__half2*)&u.z);
            float2 f3 = __half22float2(*(__half2*)&u.w);
            q[i * 8 + 0] = f0.x; q[i * 8 + 1] = f0.y; q[i * 8 + 2] = f1.x; q[i * 8 + 3] = f1.y;
            q[i * 8 + 4] = f2.x; q[i * 8 + 5] = f2.y; q[i * 8 + 6] = f3.x; q[i * 8 + 7] = f3.y;
        }
        float s[4];
#pragma unroll
        for (int ka = 0; ka < 4; ++ka) {
            float acc = 0.f;
            const char* kp = sm + KHO + (res * 4 + ka) * RS + hh * 64;
#pragma unroll
            for (int i = 0; i < 4; ++i) {
                uint4 u = *(const uint4*)(kp + i * 16);
                float2 f0 = __half22float2(*(__half2*)&u.x);
                float2 f1 = __half22float2(*(__half2*)&u.y);
                float2 f2 = __half22float2(*(__half2*)&u.z);
                float2 f3 = __half22float2(*(__half2*)&u.w);
                acc = fmaf(q[i * 8 + 0], f0.x, acc); acc = fmaf(q[i * 8 + 1], f0.y, acc);
                acc = fmaf(q[i * 8 + 2], f1.x, acc); acc = fmaf(q[i * 8 + 3], f1.y, acc);
                acc = fmaf(q[i * 8 + 4], f2.x, acc); acc = fmaf(q[i * 8 + 5], f2.y, acc);
                acc = fmaf(q[i * 8 + 6], f3.x, acc); acc = fmaf(q[i * 8 + 7], f3.y, acc);
            }
            s[ka] = (msk_f[res * 4 + ka] != 0.f) ? acc : -1e30f;
        }
        const float mx = fmaxf(fmaxf(s[0], s[1]), fmaxf(s[2], s[3]));
        float p[4], ps = 0.f;
#pragma unroll
        for (int ka = 0; ka < 4; ++ka) { p[ka] = __expf(s[ka] - mx); ps += p[ka]; }
        const float inv = 1.f / ps;

#pragma unroll
        for (int d = 0; d < 32; ++d) y[d] = 0.f;
#pragma unroll
        for (int ka = 0; ka < 4; ++ka) {
            const float pw = p[ka] * inv;
            const char* vp = sm + XH + (res * 4 + ka) * RS + hh * 64;
#pragma unroll
            for (int i = 0; i < 4; ++i) {
                uint4 u = *(const uint4*)(vp + i * 16);
                float2 f0 = __half22float2(*(__half2*)&u.x);
                float2 f1 = __half22float2(*(__half2*)&u.y);
                float2 f2 = __half22float2(*(__half2*)&u.z);
                float2 f3 = __half22float2(*(__half2*)&u.w);
                y[i * 8 + 0] = fmaf(pw, f0.x, y[i * 8 + 0]);
                y[i * 8 + 1] = fmaf(pw, f0.y, y[i * 8 + 1]);
                y[i * 8 + 2] = fmaf(pw, f1.x, y[i * 8 + 2]);
                y[i * 8 + 3] = fmaf(pw, f1.y, y[i * 8 + 3]);
                y[i * 8 + 4] = fmaf(pw, f2.x, y[i * 8 + 4]);
                y[i * 8 + 5] = fmaf(pw, f2.y, y[i * 8 + 5]);
                y[i * 8 + 6] = fmaf(pw, f3.x, y[i * 8 + 6]);
                y[i * 8 + 7] = fmaf(pw, f3.y, y[i * 8 + 7]);
            }
        }
    }
    __syncthreads();   // all Q/K/V reads done before overwriting Q with Y

    // ---- P8: write Y fp16 -> QHO ----
    {
#pragma unroll
        for (int i = 0; i < 4; ++i) {
            uint4 hv;
            uint32_t* hp = &hv.x;
#pragma unroll
            for (int gidx = 0; gidx < 4; ++gidx) {
                __half2 h = __floats2half2_rn(y[i * 8 + gidx * 2], y[i * 8 + gidx * 2 + 1]);
                hp[gidx] = *(uint32_t*)&h;
            }
            *(uint4*)(sm + QHO + tq * RS + hh * 64 + i * 16) = hv;
        }
    }
    __syncthreads();

    // ---- P9: O GEMM halves (Wo-h0 in WA, Wo-h1 in WB): out = Y·Wo^T + bo ----
    const float rma = rm_f[ra], rmb = rm_f[rb];
#pragma unroll
    for (int hf = 0; hf < 2; ++hf) {
        const uint32_t cur = hf ? WB : WA;
        float d[4][4] = {};
        warp_gemm1(sb + QHO, sb + cur, r0, nc0, d, lane);
#pragma unroll
        for (int j = 0; j < 4; ++j) {
            const int col = hf * 64 + nc0 + (j >> 1) * 16 + (j & 1) * 8 + c2;
            const float b0 = g_bias[3][col], b1 = g_bias[3][col + 1];
            float2 va, vb;
            va.x = (d[j][0] + b0) * rma; va.y = (d[j][1] + b1) * rma;
            vb.x = (d[j][2] + b0) * rmb; vb.y = (d[j][3] + b1) * rmb;
            *(float2*)(out + (tok0 + ra) * C + col) = va;
            *(float2*)(out + (tok0 + rb) * C + col) = vb;
        }
    }
}

extern "C" void kernel_launch(void* const* d_in, const int* in_sizes, int n_in,
                              void* d_out, int out_size)
{
    const float* x    = (const float*)d_in[0];
    const int*   mask = (const int*)d_in[1];
    const float* Wq = (const float*)d_in[2];
    const float* bq = (const float*)d_in[3];
    const float* Wk = (const float*)d_in[4];
    const float* bk = (const float*)d_in[5];
    const float* Wv = (const float*)d_in[6];
    const float* bv = (const float*)d_in[7];
    const float* Wo = (const float*)d_in[8];
    const float* bo = (const float*)d_in[9];
    float* out = (float*)d_out;

    const int ntok = in_sizes[0] / laa::C;      // 262144
    const int nblk = ntok / laa::TOKS;          // 4096

    prep_split<<<4, 256>>>(Wq, bq, Wk, bk, Wv, bv, Wo, bo);

    cudaFuncSetAttribute(laa_mma_kernel,
                         cudaFuncAttributeMaxDynamicSharedMemorySize, laa::TOTAL);
    laa_mma_kernel<<<nblk, laa::NT, laa::TOTAL>>>(x, mask, out);
}

// round 9
// speedup vs baseline: 7.3074x; 1.0689x over previous
#include <cuda_runtime.h>
#include <cuda_fp16.h>
#include <cstdint>

// LocalAtomAttention (round 9): mma.sync fp16, 32x32 warp tiles (full-width
// single-pass GEMMs), W prefetch into dead smem regions, 64-tok CTAs, 2/SM.
// Phases: P0 Q gemm; P1 K gemm (Wk pre-staged in KHO region); P2 V gemm;
// P3 attention; P4 O gemm.  Staging: Wq,Wk behind X-load; Wv behind K gemm;
// Wo behind attention.

namespace laa {
constexpr int C = 128, TOKS = 64, NT = 256;
constexpr uint32_t RS = 272;            // smem row stride bytes
constexpr uint32_t XH = 0, QHO = 17408, KHO = 34816 /*34816B: Wk then K*/,
                   W = 69632, MSK = 104448, RM = 104704,
                   TOTAL = 104960;      // x2 CTAs = 209,920 <= 228KB/SM
constexpr float SCALE = 0.17677669529663687f;  // 1/sqrt(32)
}

// Prepped fp16 weights: [4] = {Wq*s, Wk, Wv, Wo}, 272B rows, 34816B each.
__device__ __align__(16) unsigned char g_wimg[4][34816];
__device__ float g_bias[4][128];   // {bq*s, bk, bv, bo}

// ---------------- helpers ----------------
__device__ __forceinline__ uint32_t smem_u32(const void* p) {
    uint32_t a;
    asm("{ .reg .u64 t; cvta.to.shared.u64 t, %1; cvt.u32.u64 %0, t; }" : "=r"(a) : "l"(p));
    return a;
}
__device__ __forceinline__ void ldsm4(uint32_t& a0, uint32_t& a1, uint32_t& a2,
                                      uint32_t& a3, uint32_t addr) {
    asm volatile("ldmatrix.sync.aligned.m8n8.x4.shared.b16 {%0,%1,%2,%3}, [%4];"
                 : "=r"(a0), "=r"(a1), "=r"(a2), "=r"(a3) : "r"(addr));
}
__device__ __forceinline__ void mma16816(float d[4], uint32_t a0, uint32_t a1,
                                         uint32_t a2, uint32_t a3,
                                         uint32_t b0, uint32_t b1) {
    asm volatile(
        "mma.sync.aligned.m16n8k16.row.col.f32.f16.f16.f32 "
        "{%0,%1,%2,%3}, {%4,%5,%6,%7}, {%8,%9}, {%0,%1,%2,%3};"
        : "+f"(d[0]), "+f"(d[1]), "+f"(d[2]), "+f"(d[3])
        : "r"(a0), "r"(a1), "r"(a2), "r"(a3), "r"(b0), "r"(b1));
}
__device__ __forceinline__ void cpa16(uint32_t dst, const unsigned char* src) {
    uint64_t g;
    asm("cvta.to.global.u64 %0, %1;" : "=l"(g) : "l"(src));
    asm volatile("cp.async.cg.shared.global [%0], [%1], 16;" :: "r"(dst), "l"(g));
}
#define CPA_COMMIT() asm volatile("cp.async.commit_group;" ::: "memory")
#define CPA_WAIT0()  asm volatile("cp.async.wait_group 0;" ::: "memory")

// ---------------- prep kernel ----------------
__global__ void prep_split(const float* __restrict__ Wq, const float* __restrict__ bq,
                           const float* __restrict__ Wk, const float* __restrict__ bk,
                           const float* __restrict__ Wv, const float* __restrict__ bv,
                           const float* __restrict__ Wo, const float* __restrict__ bo) {
    int m = blockIdx.x;
    const float* src  = (m == 0) ? Wq : (m == 1) ? Wk : (m == 2) ? Wv : Wo;
    const float* bsrc = (m == 0) ? bq : (m == 1) ? bk : (m == 2) ? bv : bo;
    float sc = (m == 0) ? laa::SCALE : 1.f;
    unsigned char* img = g_wimg[m];
    for (int i = threadIdx.x; i < 16384; i += blockDim.x) {
        int row = i >> 7, col = i & 127;
        *(__half*)(img + row * laa::RS + col * 2) = __float2half_rn(src[i] * sc);
    }
    if (threadIdx.x < 128) g_bias[m][threadIdx.x] = bsrc[threadIdx.x] * sc;
}

// ---------------- main kernel ----------------
using namespace laa;

// Warp GEMM: D[32 rows x 32 cols] += A·B^T over K=128 (fp16 operands).
__device__ __forceinline__ void warp_gemm32(uint32_t a_t, uint32_t wbuf,
                                            int r0, int nc0, float d[2][4][4],
                                            int lane) {
    const uint32_t aoff = (uint32_t)(r0 + (lane & 15)) * RS + ((lane >> 4) << 4);
    const uint32_t brow = (lane & 7) + ((lane & 16) >> 1);
    const uint32_t bkof = (lane & 8) << 1;
#pragma unroll
    for (int ks = 0; ks < 8; ++ks) {
        const uint32_t kb = ks * 32;
        uint32_t a0, a1, a2, a3, a4, a5, a6, a7;
        ldsm4(a0, a1, a2, a3, a_t + aoff + kb);
        ldsm4(a4, a5, a6, a7, a_t + aoff + 16 * RS + kb);
#pragma unroll
        for (int np = 0; np < 2; ++np) {
            const uint32_t ba = (uint32_t)(nc0 + np * 16 + brow) * RS + bkof + kb;
            uint32_t b0, b1, b2, b3;
            ldsm4(b0, b1, b2, b3, wbuf + ba);
            mma16816(d[0][2 * np],     a0, a1, a2, a3, b0, b1);
            mma16816(d[0][2 * np + 1], a0, a1, a2, a3, b2, b3);
            mma16816(d[1][2 * np],     a4, a5, a6, a7, b0, b1);
            mma16816(d[1][2 * np + 1], a4, a5, a6, a7, b2, b3);
        }
    }
}

// Stage full W matrix m (34816 B) into dst via cp.async.
__device__ __forceinline__ void stage_w(uint32_t dst, int m, int tid) {
    const unsigned char* src = g_wimg[m];
#pragma unroll 2
    for (int i = tid; i < 2176; i += NT) cpa16(dst + i * 16, src + i * 16);
    CPA_COMMIT();
}

__global__ __launch_bounds__(NT, 2)
void laa_mma_kernel(const float* __restrict__ x, const int* __restrict__ mask,
                    float* __restrict__ out)
{
    extern __shared__ __align__(16) char sm[];
    const uint32_t sb = smem_u32(sm);
    const int tid = threadIdx.x, lane = tid & 31, w = tid >> 5;
    const long long tok0 = (long long)blockIdx.x * TOKS;

    float* msk_f = (float*)(sm + MSK);
    float* rm_f  = (float*)(sm + RM);

    // ---- P-1: stage Wq->W and Wk->KHO; X load + fp16 convert; masks ----
    stage_w(sb + W, 0, tid);
    stage_w(sb + KHO, 1, tid);
#pragma unroll
    for (int it = 0; it < 8; ++it) {
        int idx = it * NT + tid;              // float4 index over [64][32]
        int row = idx >> 5, c4 = idx & 31;
        float4 v = __ldg((const float4*)x + (tok0 + row) * 32 + c4);
        __half2 h01 = __floats2half2_rn(v.x, v.y);
        __half2 h23 = __floats2half2_rn(v.z, v.w);
        uint2 hv;
        hv.x = *(uint32_t*)&h01; hv.y = *(uint32_t*)&h23;
        *(uint2*)(sm + XH + row * RS + c4 * 8) = hv;
    }
    if (tid < TOKS) {
        msk_f[tid] = (__ldg(&mask[tok0 + tid]) != 0) ? 1.f : 0.f;
        long long b = tok0 + (tid & ~3);
        int any = __ldg(&mask[b]) | __ldg(&mask[b + 1]) | __ldg(&mask[b + 2]) | __ldg(&mask[b + 3]);
        rm_f[tid] = (any != 0) ? 1.f : 0.f;
    }
    CPA_WAIT0();
    __syncthreads();

    const int r0 = (w >> 2) * 32;             // {0,32}
    const int nc0 = (w & 3) * 32;             // {0,32,64,96}
    const int rq = lane >> 2;
    const int c2 = 2 * (lane & 3);

    // ---- P0: Q GEMM (B=Wq in W) -> write QHO fp16 ----
    {
        float d[2][4][4] = {};
        warp_gemm32(sb + XH, sb + W, r0, nc0, d, lane);
#pragma unroll
        for (int mi = 0; mi < 2; ++mi) {
            const int ra = r0 + mi * 16 + rq, rb = ra + 8;
#pragma unroll
            for (int j = 0; j < 4; ++j) {
                const int col = nc0 + (j >> 1) * 16 + (j & 1) * 8 + c2;
                const float b0 = g_bias[0][col], b1 = g_bias[0][col + 1];
                *(__half2*)(sm + QHO + ra * RS + col * 2) =
                    __floats2half2_rn(d[mi][j][0] + b0, d[mi][j][1] + b1);
                *(__half2*)(sm + QHO + rb * RS + col * 2) =
                    __floats2half2_rn(d[mi][j][2] + b0, d[mi][j][3] + b1);
            }
        }
    }
    __syncthreads();                          // Wq reads done

    // ---- P1: stage Wv->W; K GEMM (B=Wk in KHO); then write K->KHO ----
    stage_w(sb + W, 2, tid);
    {
        float d[2][4][4] = {};
        warp_gemm32(sb + XH, sb + KHO, r0, nc0, d, lane);
        __syncthreads();                      // all Wk reads done
#pragma unroll
        for (int mi = 0; mi < 2; ++mi) {
            const int ra = r0 + mi * 16 + rq, rb = ra + 8;
#pragma unroll
            for (int j = 0; j < 4; ++j) {
                const int col = nc0 + (j >> 1) * 16 + (j & 1) * 8 + c2;
                const float b0 = g_bias[1][col], b1 = g_bias[1][col + 1];
                *(__half2*)(sm + KHO + ra * RS + col * 2) =
                    __floats2half2_rn(d[mi][j][0] + b0, d[mi][j][1] + b1);
                *(__half2*)(sm + KHO + rb * RS + col * 2) =
                    __floats2half2_rn(d[mi][j][2] + b0, d[mi][j][3] + b1);
            }
        }
    }
    CPA_WAIT0();                              // Wv staged
    __syncthreads();                          // K visible

    // ---- P2: V GEMM (B=Wv in W); stage Wo->W after reads; write V->XH ----
    {
        float d[2][4][4] = {};
        warp_gemm32(sb + XH, sb + W, r0, nc0, d, lane);
        __syncthreads();                      // X and Wv reads done
        stage_w(sb + W, 3, tid);              // Wo staging hides behind attention
#pragma unroll
        for (int mi = 0; mi < 2; ++mi) {
            const int ra = r0 + mi * 16 + rq, rb = ra + 8;
#pragma unroll
            for (int j = 0; j < 4; ++j) {
                const int col = nc0 + (j >> 1) * 16 + (j & 1) * 8 + c2;
                const float b0 = g_bias[2][col], b1 = g_bias[2][col + 1];
                *(__half2*)(sm + XH + ra * RS + col * 2) =
                    __floats2half2_rn(d[mi][j][0] + b0, d[mi][j][1] + b1);
                *(__half2*)(sm + XH + rb * RS + col * 2) =
                    __floats2half2_rn(d[mi][j][2] + b0, d[mi][j][3] + b1);
            }
        }
    }
    __syncthreads();                          // V visible

    // ---- P3: attention, one unit per thread (res, h, qa); y = P·v_head ----
    float y[32];
    int tq, hh;
    {
        const int res = tid >> 4;
        hh = (tid >> 2) & 3;
        const int qa = tid & 3;
        tq = res * 4 + qa;

        float q[32];
#pragma unroll
        for (int i = 0; i < 4; ++i) {
            uint4 u = *(const uint4*)(sm + QHO + tq * RS + hh * 64 + i * 16);
            float2 f0 = __half22float2(*(__half2*)&u.x);
            float2 f1 = __half22float2(*(__half2*)&u.y);
            float2 f2 = __half22float2(*(__half2*)&u.z);
            float2 f3 = __half22float2(*(__half2*)&u.w);
            q[i * 8 + 0] = f0.x; q[i * 8 + 1] = f0.y; q[i * 8 + 2] = f1.x; q[i * 8 + 3] = f1.y;
            q[i * 8 + 4] = f2.x; q[i * 8 + 5] = f2.y; q[i * 8 + 6] = f3.x; q[i * 8 + 7] = f3.y;
        }
        float s[4];
#pragma unroll
        for (int ka = 0; ka < 4; ++ka) {
            float acc = 0.f;
            const char* kp = sm + KHO + (res * 4 + ka) * RS + hh * 64;
#pragma unroll
            for (int i = 0; i < 4; ++i) {
                uint4 u = *(const uint4*)(kp + i * 16);
                float2 f0 = __half22float2(*(__half2*)&u.x);
                float2 f1 = __half22float2(*(__half2*)&u.y);
                float2 f2 = __half22float2(*(__half2*)&u.z);
                float2 f3 = __half22float2(*(__half2*)&u.w);
                acc = fmaf(q[i * 8 + 0], f0.x, acc); acc = fmaf(q[i * 8 + 1], f0.y, acc);
                acc = fmaf(q[i * 8 + 2], f1.x, acc); acc = fmaf(q[i * 8 + 3], f1.y, acc);
                acc = fmaf(q[i * 8 + 4], f2.x, acc); acc = fmaf(q[i * 8 + 5], f2.y, acc);
                acc = fmaf(q[i * 8 + 6], f3.x, acc); acc = fmaf(q[i * 8 + 7], f3.y, acc);
            }
            s[ka] = (msk_f[res * 4 + ka] != 0.f) ? acc : -1e30f;
        }
        const float mx = fmaxf(fmaxf(s[0], s[1]), fmaxf(s[2], s[3]));
        float p[4], ps = 0.f;
#pragma unroll
        for (int ka = 0; ka < 4; ++ka) { p[ka] = __expf(s[ka] - mx); ps += p[ka]; }
        const float inv = 1.f / ps;

#pragma unroll
        for (int d = 0; d < 32; ++d) y[d] = 0.f;
#pragma unroll
        for (int ka = 0; ka < 4; ++ka) {
            const float pw = p[ka] * inv;
            const char* vp = sm + XH + (res * 4 + ka) * RS + hh * 64;
#pragma unroll
            for (int i = 0; i < 4; ++i) {
                uint4 u = *(const uint4*)(vp + i * 16);
                float2 f0 = __half22float2(*(__half2*)&u.x);
                float2 f1 = __half22float2(*(__half2*)&u.y);
                float2 f2 = __half22float2(*(__half2*)&u.z);
                float2 f3 = __half22float2(*(__half2*)&u.w);
                y[i * 8 + 0] = fmaf(pw, f0.x, y[i * 8 + 0]);
                y[i * 8 + 1] = fmaf(pw, f0.y, y[i * 8 + 1]);
                y[i * 8 + 2] = fmaf(pw, f1.x, y[i * 8 + 2]);
                y[i * 8 + 3] = fmaf(pw, f1.y, y[i * 8 + 3]);
                y[i * 8 + 4] = fmaf(pw, f2.x, y[i * 8 + 4]);
                y[i * 8 + 5] = fmaf(pw, f2.y, y[i * 8 + 5]);
                y[i * 8 + 6] = fmaf(pw, f3.x, y[i * 8 + 6]);
                y[i * 8 + 7] = fmaf(pw, f3.y, y[i * 8 + 7]);
            }
        }
    }
    __syncthreads();                          // Q reads done before Y overwrite

    // ---- write Y fp16 -> QHO; wait Wo ----
    {
#pragma unroll
        for (int i = 0; i < 4; ++i) {
            uint4 hv;
            uint32_t* hp = &hv.x;
#pragma unroll
            for (int gidx = 0; gidx < 4; ++gidx) {
                __half2 h = __floats2half2_rn(y[i * 8 + gidx * 2], y[i * 8 + gidx * 2 + 1]);
                hp[gidx] = *(uint32_t*)&h;
            }
            *(uint4*)(sm + QHO + tq * RS + hh * 64 + i * 16) = hv;
        }
    }
    CPA_WAIT0();                              // Wo staged
    __syncthreads();                          // Y visible

    // ---- P4: O GEMM (A=Y in QHO, B=Wo in W): out = Y·Wo^T + bo ----
    {
        float d[2][4][4] = {};
        warp_gemm32(sb + QHO, sb + W, r0, nc0, d, lane);
#pragma unroll
        for (int mi = 0; mi < 2; ++mi) {
            const int ra = r0 + mi * 16 + rq, rb = ra + 8;
            const float rma = rm_f[ra], rmb = rm_f[rb];
#pragma unroll
            for (int j = 0; j < 4; ++j) {
                const int col = nc0 + (j >> 1) * 16 + (j & 1) * 8 + c2;
                const float b0 = g_bias[3][col], b1 = g_bias[3][col + 1];
                float2 va, vb;
                va.x = (d[mi][j][0] + b0) * rma; va.y = (d[mi][j][1] + b1) * rma;
                vb.x = (d[mi][j][2] + b0) * rmb; vb.y = (d[mi][j][3] + b1) * rmb;
                *(float2*)(out + (tok0 + ra) * C + col) = va;
                *(float2*)(out + (tok0 + rb) * C + col) = vb;
            }
        }
    }
}

extern "C" void kernel_launch(void* const* d_in, const int* in_sizes, int n_in,
                              void* d_out, int out_size)
{
    const float* x    = (const float*)d_in[0];
    const int*   mask = (const int*)d_in[1];
    const float* Wq = (const float*)d_in[2];
    const float* bq = (const float*)d_in[3];
    const float* Wk = (const float*)d_in[4];
    const float* bk = (const float*)d_in[5];
    const float* Wv = (const float*)d_in[6];
    const float* bv = (const float*)d_in[7];
    const float* Wo = (const float*)d_in[8];
    const float* bo = (const float*)d_in[9];
    float* out = (float*)d_out;

    const int ntok = in_sizes[0] / laa::C;      // 262144
    const int nblk = ntok / laa::TOKS;          // 4096

    prep_split<<<4, 256>>>(Wq, bq, Wk, bk, Wv, bv, Wo, bo);

    cudaFuncSetAttribute(laa_mma_kernel,
                         cudaFuncAttributeMaxDynamicSharedMemorySize, laa::TOTAL);
    laa_mma_kernel<<<nblk, laa::NT, laa::TOTAL>>>(x, mask, out);
}